// round 10
// baseline (speedup 1.0000x reference)
#include <cuda_runtime.h>
#include <math.h>

#define BB   4
#define C8   8
#define C16  16
#define FF   256
#define TN   2000
#define CHW  (FF*TN)
#define TWO_PI_F     6.283185307179586f
#define INV_TWO_PI_F 0.15915494309189535f

typedef unsigned long long ull;

__device__ float g_s1[BB*2*C16*CHW];

__device__ __forceinline__ float mod2pi(float a) {
    return a - floorf(a * INV_TWO_PI_F) * TWO_PI_F;
}

// ---- f32x2 helpers (kA only) ----
__device__ __forceinline__ ull pk(float lo, float hi) {
    ull r; asm("mov.b64 %0,{%1,%2};" : "=l"(r) : "f"(lo), "f"(hi)); return r;
}
__device__ __forceinline__ void upk(ull v, float& lo, float& hi) {
    asm("mov.b64 {%0,%1},%2;" : "=f"(lo), "=f"(hi) : "l"(v));
}
__device__ __forceinline__ ull ffma2(ull a, ull b, ull c) {
    ull d; asm("fma.rn.f32x2 %0,%1,%2,%3;" : "=l"(d) : "l"(a), "l"(b), "l"(c)); return d;
}
__device__ __forceinline__ ull ld64(const float* p) {
    return *reinterpret_cast<const ull*>(p);
}
__device__ __forceinline__ void st64(float* p, ull v) {
    *reinterpret_cast<ull*>(p) = v;
}

// ---------------------------------------------------------------------------
// Kernel A: cLog -> channel_shuffle (8->16) -> cAct.  2 timesteps per thread.
// (measured ~105 us, stable across rounds)
// ---------------------------------------------------------------------------
__global__ void kA(const float* __restrict__ x,
                   const float* __restrict__ wr, const float* __restrict__ wi,
                   const float* __restrict__ br, const float* __restrict__ bi)
{
    const int f = blockIdx.y;
    const int b = blockIdx.z;

    __shared__ ull swr2[C16*C8], swi2[C16*C8];
    __shared__ ull sbr2[C16], sbi2[C16];
    for (int i = threadIdx.x; i < C16*C8; i += blockDim.x) {
        float a = wr[f*C16*C8 + i]; swr2[i] = pk(a, a);
        float c = wi[f*C16*C8 + i]; swi2[i] = pk(c, c);
    }
    if (threadIdx.x < C16) {
        float a = br[f*C16 + threadIdx.x]; sbr2[threadIdx.x] = pk(a, a);
        float c = bi[f*C16 + threadIdx.x]; sbi2[threadIdx.x] = pk(c, c);
    }
    __syncthreads();

    const int tp = 2 * (blockIdx.x * blockDim.x + threadIdx.x);
    if (tp >= TN) return;
    const int off = f*TN + tp;

    ull lm2[C8], ph2[C8];
    #pragma unroll
    for (int c = 0; c < C8; c++) {
        ull xr = ld64(x + ((b*2+0)*C8 + c)*CHW + off);
        ull xi = ld64(x + ((b*2+1)*C8 + c)*CHW + off);
        float r0, r1, i0, i1;
        upk(xr, r0, r1); upk(xi, i0, i1);
        float l0 = 0.5f * __logf(fmaf(r0, r0, fmaf(i0, i0, 1e-12f)));
        float l1 = 0.5f * __logf(fmaf(r1, r1, fmaf(i1, i1, 1e-12f)));
        lm2[c] = pk(l0, l1);
        ph2[c] = pk(atan2f(i0, r0), atan2f(i1, r1));
    }
    #pragma unroll
    for (int o = 0; o < C16; o++) {
        ull sr = sbr2[o], si = sbi2[o];
        #pragma unroll
        for (int c = 0; c < C8; c++) {
            sr = ffma2(swr2[o*C8+c], lm2[c], sr);
            si = ffma2(swi2[o*C8+c], ph2[c], si);
        }
        float s0, s1, p0, p1;
        upk(sr, s0, s1); upk(si, p0, p1);
        float w0 = (__cosf(p0) + 1.0f) * 0.5f;
        float w1 = (__cosf(p1) + 1.0f) * 0.5f;
        st64(g_s1 + ((b*2+0)*C16 + o)*CHW + off, pk(w0*s0, w1*s1));
        st64(g_s1 + ((b*2+1)*C16 + o)*CHW + off, pk(mod2pi(p0), mod2pi(p1)));
    }
}

// ---------------------------------------------------------------------------
// Fused kernel BC:
//  Phase 1: freq_conv(5, zero-pad) + cAct from g_s1 -> SMEM s2 tile
//  Phase 2: time_conv (taps from SMEM) -> cExp -> ls -> cMul(x) -> la -> out
// block = (t_chunk of 256, f, b); 128 threads; 1 t-pair per thread.
// ---------------------------------------------------------------------------
#define TC2    256
#define T_EXT  (TC2 + 9)     // 265: taps reach t0+1+8
#define T_PAD  268           // even, 16B-friendly

__global__ void __launch_bounds__(128, 3) kBC(
    const float* __restrict__ x,
    const float* __restrict__ fcwr, const float* __restrict__ fcwi,
    const float* __restrict__ fcbr, const float* __restrict__ fcbi,
    const float* __restrict__ twr, const float* __restrict__ twi,
    const float* __restrict__ tbr, const float* __restrict__ tbi,
    const float* __restrict__ lwr, const float* __restrict__ lwi,
    const float* __restrict__ lbr, const float* __restrict__ lbi,
    const float* __restrict__ awr, const float* __restrict__ awi,
    const float* __restrict__ abr, const float* __restrict__ abi,
    float* __restrict__ out)
{
    const int f     = blockIdx.y;
    const int b     = blockIdx.z;
    const int tBase = blockIdx.x * TC2;
    const int tid   = threadIdx.x;

    __shared__ __align__(16) float s2t[2*C16*T_PAD];                // [(c*2+ri)*T_PAD + tl]
    __shared__ __align__(16) float stwr[C8*C16*5], stwi[C8*C16*5];  // [(c*5+k)*8+o]
    __shared__ float slwr[64], slwi[64], sawr[64], sawi[64];        // [o*8+c]
    __shared__ float sfcw[160], sfcb[32];                           // fc weights/biases
    __shared__ float stbr[8], stbi[8], slbr[8], slbi[8], sabr[8], sabi[8];

    // ---- stage weights ----
    for (int i = tid; i < C8*C16*5; i += 128) {
        int o = i & 7, ck = i >> 3;
        int c = ck / 5, k = ck - 5*c;
        stwr[i] = twr[f*C8*C16*5 + (o*C16 + c)*5 + k];
        stwi[i] = twi[f*C8*C16*5 + (o*C16 + c)*5 + k];
    }
    if (tid < 64) {
        slwr[tid] = lwr[f*64 + tid];
        slwi[tid] = lwi[f*64 + tid];
        sawr[tid] = awr[f*64 + tid];
        sawi[tid] = awi[f*64 + tid];
    }
    if (tid < 80) {
        sfcw[tid]      = fcwr[tid];
        sfcw[80 + tid] = fcwi[tid];
    } else if (tid < 112) {
        int c = tid - 80;   // 0..31
        if (c < 16) sfcb[c] = fcbr[c];
        else        sfcb[c] = fcbi[c - 16];
    }
    if (tid < 8) {
        stbr[tid] = tbr[f*8 + tid];
        stbi[tid] = tbi[f*8 + tid];
        slbr[tid] = lbr[f*8 + tid];
        slbi[tid] = lbi[f*8 + tid];
        sabr[tid] = abr[f*8 + tid];
        sabi[tid] = abi[f*8 + tid];
    }
    __syncthreads();

    // ---- phase 1: s2 tile (freq_conv + cAct), zero-filled beyond TN ----
    {
        const float* s1r_base = g_s1 + (b*2+0)*C16*CHW;
        const float* s1i_base = g_s1 + (b*2+1)*C16*CHW;
        #pragma unroll 1
        for (int c = 0; c < C16; c++) {
            const float wr0 = sfcw[c*5+0], wr1 = sfcw[c*5+1], wr2 = sfcw[c*5+2],
                        wr3 = sfcw[c*5+3], wr4 = sfcw[c*5+4];
            const float wi0 = sfcw[80+c*5+0], wi1 = sfcw[80+c*5+1], wi2 = sfcw[80+c*5+2],
                        wi3 = sfcw[80+c*5+3], wi4 = sfcw[80+c*5+4];
            const float br_ = sfcb[c], bi_ = sfcb[16+c];
            const float* pr = s1r_base + c*CHW;
            const float* pi = s1i_base + c*CHW;
            for (int tl = tid; tl < T_EXT; tl += 128) {
                const int tt = tBase + tl;
                float vr = 0.0f, vi = 0.0f;
                if (tt < TN) {
                    float yr = br_, yi = bi_;
                    const int o0 = tt;  // f offsets guarded below
                    if (f >= 2)      { yr = fmaf(wr0, pr[(f-2)*TN + o0], yr); yi = fmaf(wi0, pi[(f-2)*TN + o0], yi); }
                    if (f >= 1)      { yr = fmaf(wr1, pr[(f-1)*TN + o0], yr); yi = fmaf(wi1, pi[(f-1)*TN + o0], yi); }
                    {                  yr = fmaf(wr2, pr[(f  )*TN + o0], yr); yi = fmaf(wi2, pi[(f  )*TN + o0], yi); }
                    if (f <= FF-2)   { yr = fmaf(wr3, pr[(f+1)*TN + o0], yr); yi = fmaf(wi3, pi[(f+1)*TN + o0], yi); }
                    if (f <= FF-3)   { yr = fmaf(wr4, pr[(f+2)*TN + o0], yr); yi = fmaf(wi4, pi[(f+2)*TN + o0], yi); }
                    float w = (__cosf(yi) + 1.0f) * 0.5f;
                    vr = w * yr;
                    vi = mod2pi(yi);
                }
                s2t[(c*2+0)*T_PAD + tl] = vr;
                s2t[(c*2+1)*T_PAD + tl] = vi;
            }
        }
    }
    __syncthreads();

    // ---- phase 2: one t-pair per thread ----
    const int t0 = tBase + 2*tid;
    if (t0 >= TN) return;
    const int tl0 = 2*tid;

    const float* xr_p = x + (b*2+0)*C8*CHW + f*TN;
    const float* xi_p = x + (b*2+1)*C8*CHW + f*TN;
    float* outr = out + (b*2+0)*C8*CHW + f*TN;
    float* outi = out + (b*2+1)*C8*CHW + f*TN;

    float ar[8][2], ai[8][2];
    #pragma unroll
    for (int o = 0; o < 8; o++) {
        ar[o][0] = stbr[o]; ar[o][1] = stbr[o];
        ai[o][0] = stbi[o]; ai[o][1] = stbi[o];
    }

    #pragma unroll
    for (int c = 0; c < C16; c++) {
        float vr[10], vi[10];
        #pragma unroll
        for (int m = 0; m < 5; m++) {
            float2 a = *reinterpret_cast<const float2*>(&s2t[(c*2+0)*T_PAD + tl0 + 2*m]);
            float2 d = *reinterpret_cast<const float2*>(&s2t[(c*2+1)*T_PAD + tl0 + 2*m]);
            vr[2*m] = a.x; vr[2*m+1] = a.y;
            vi[2*m] = d.x; vi[2*m+1] = d.y;
        }
        #pragma unroll
        for (int k = 0; k < 5; k++) {
            const float4 w0 = *reinterpret_cast<const float4*>(stwr + (c*5+k)*8);
            const float4 w1 = *reinterpret_cast<const float4*>(stwr + (c*5+k)*8 + 4);
            const float4 u0 = *reinterpret_cast<const float4*>(stwi + (c*5+k)*8);
            const float4 u1 = *reinterpret_cast<const float4*>(stwi + (c*5+k)*8 + 4);
            const float wrs[8] = {w0.x, w0.y, w0.z, w0.w, w1.x, w1.y, w1.z, w1.w};
            const float wis[8] = {u0.x, u0.y, u0.z, u0.w, u1.x, u1.y, u1.z, u1.w};
            #pragma unroll
            for (int o = 0; o < 8; o++) {
                ar[o][0] = fmaf(wrs[o], vr[2*k],   ar[o][0]);
                ar[o][1] = fmaf(wrs[o], vr[2*k+1], ar[o][1]);
                ai[o][0] = fmaf(wis[o], vi[2*k],   ai[o][0]);
                ai[o][1] = fmaf(wis[o], vi[2*k+1], ai[o][1]);
            }
        }
    }

    float orj[8][2], oij[8][2];
    #pragma unroll
    for (int j = 0; j < 2; j++) {
        // cExp
        float er[8], ei[8];
        #pragma unroll
        for (int o = 0; o < 8; o++) {
            float r = __expf(ar[o][j]);
            float sn, cs;
            __sincosf(ai[o][j], &sn, &cs);
            er[o] = r * cs;
            ei[o] = r * sn;
        }
        // last_shuffle (complex 8x8)
        float sr[8], si[8];
        #pragma unroll
        for (int o = 0; o < 8; o++) {
            float yr = slbr[o] - slbi[o];
            float yi = slbr[o] + slbi[o];
            #pragma unroll
            for (int c = 0; c < 8; c++) {
                float wr_ = slwr[o*8+c], wi_ = slwi[o*8+c];
                yr = fmaf(wr_, er[c], yr);
                yr = fmaf(-wi_, ei[c], yr);
                yi = fmaf(wr_, ei[c], yi);
                yi = fmaf(wi_, er[c], yi);
            }
            sr[o] = yr; si[o] = yi;
        }
        // cMul with x
        #pragma unroll
        for (int c = 0; c < 8; c++) {
            float vxr = xr_p[c*CHW + t0 + j];
            float vxi = xi_p[c*CHW + t0 + j];
            float mr = sr[c]*vxr - si[c]*vxi;
            float mi = sr[c]*vxi + si[c]*vxr;
            sr[c] = mr; si[c] = mi;
        }
        // last (complex 8x8)
        #pragma unroll
        for (int o = 0; o < 8; o++) {
            float yr = sabr[o] - sabi[o];
            float yi = sabr[o] + sabi[o];
            #pragma unroll
            for (int c = 0; c < 8; c++) {
                float wr_ = sawr[o*8+c], wi_ = sawi[o*8+c];
                yr = fmaf(wr_, sr[c], yr);
                yr = fmaf(-wi_, si[c], yr);
                yi = fmaf(wr_, si[c], yi);
                yi = fmaf(wi_, sr[c], yi);
            }
            orj[o][j] = yr; oij[o][j] = yi;
        }
    }
    #pragma unroll
    for (int o = 0; o < 8; o++) {
        *reinterpret_cast<float2*>(outr + o*CHW + t0) = make_float2(orj[o][0], orj[o][1]);
        *reinterpret_cast<float2*>(outi + o*CHW + t0) = make_float2(oij[o][0], oij[o][1]);
    }
}

// ---------------------------------------------------------------------------
extern "C" void kernel_launch(void* const* d_in, const int* in_sizes, int n_in,
                              void* d_out, int out_size)
{
    const float* x     = (const float*)d_in[0];
    const float* cs_wr = (const float*)d_in[1];
    const float* cs_wi = (const float*)d_in[2];
    const float* cs_br = (const float*)d_in[3];
    const float* cs_bi = (const float*)d_in[4];
    const float* fc_wr = (const float*)d_in[5];
    const float* fc_wi = (const float*)d_in[6];
    const float* fc_br = (const float*)d_in[7];
    const float* fc_bi = (const float*)d_in[8];
    const float* tc_wr = (const float*)d_in[9];
    const float* tc_wi = (const float*)d_in[10];
    const float* tc_br = (const float*)d_in[11];
    const float* tc_bi = (const float*)d_in[12];
    const float* ls_wr = (const float*)d_in[13];
    const float* ls_wi = (const float*)d_in[14];
    const float* ls_br = (const float*)d_in[15];
    const float* ls_bi = (const float*)d_in[16];
    const float* la_wr = (const float*)d_in[17];
    const float* la_wi = (const float*)d_in[18];
    const float* la_br = (const float*)d_in[19];
    const float* la_bi = (const float*)d_in[20];
    float* out = (float*)d_out;

    dim3 gA((TN/2 + 255)/256, FF, BB);
    kA<<<gA, 256>>>(x, cs_wr, cs_wi, cs_br, cs_bi);

    dim3 gBC((TN + TC2 - 1)/TC2, FF, BB);   // 8, 256, 4
    kBC<<<gBC, 128>>>(x, fc_wr, fc_wi, fc_br, fc_bi,
                      tc_wr, tc_wi, tc_br, tc_bi,
                      ls_wr, ls_wi, ls_br, ls_bi,
                      la_wr, la_wi, la_br, la_bi, out);
}

// round 11
// speedup vs baseline: 1.1446x; 1.1446x over previous
#include <cuda_runtime.h>
#include <math.h>

#define BB   4
#define C8   8
#define C16  16
#define FF   256
#define TN   2000
#define CHW  (FF*TN)
#define TWO_PI_F     6.283185307179586f
#define INV_TWO_PI_F 0.15915494309189535f

typedef unsigned long long ull;

__device__ float g_s1[BB*2*C16*CHW];
__device__ float g_s2[BB*2*C16*CHW];

__device__ __forceinline__ float mod2pi(float a) {
    return a - floorf(a * INV_TWO_PI_F) * TWO_PI_F;
}

// ---- f32x2 helpers (kA/kB only) ----
__device__ __forceinline__ ull pk(float lo, float hi) {
    ull r; asm("mov.b64 %0,{%1,%2};" : "=l"(r) : "f"(lo), "f"(hi)); return r;
}
__device__ __forceinline__ void upk(ull v, float& lo, float& hi) {
    asm("mov.b64 {%0,%1},%2;" : "=f"(lo), "=f"(hi) : "l"(v));
}
__device__ __forceinline__ ull ffma2(ull a, ull b, ull c) {
    ull d; asm("fma.rn.f32x2 %0,%1,%2,%3;" : "=l"(d) : "l"(a), "l"(b), "l"(c)); return d;
}
__device__ __forceinline__ ull ld64(const float* p) {
    return *reinterpret_cast<const ull*>(p);
}
__device__ __forceinline__ void st64(float* p, ull v) {
    *reinterpret_cast<ull*>(p) = v;
}

// ---------------------------------------------------------------------------
// Kernel A: cLog -> channel_shuffle (8->16) -> cAct.  2 timesteps per thread.
// (measured ~105 us, stable — unchanged)
// ---------------------------------------------------------------------------
__global__ void kA(const float* __restrict__ x,
                   const float* __restrict__ wr, const float* __restrict__ wi,
                   const float* __restrict__ br, const float* __restrict__ bi)
{
    const int f = blockIdx.y;
    const int b = blockIdx.z;

    __shared__ ull swr2[C16*C8], swi2[C16*C8];
    __shared__ ull sbr2[C16], sbi2[C16];
    for (int i = threadIdx.x; i < C16*C8; i += blockDim.x) {
        float a = wr[f*C16*C8 + i]; swr2[i] = pk(a, a);
        float c = wi[f*C16*C8 + i]; swi2[i] = pk(c, c);
    }
    if (threadIdx.x < C16) {
        float a = br[f*C16 + threadIdx.x]; sbr2[threadIdx.x] = pk(a, a);
        float c = bi[f*C16 + threadIdx.x]; sbi2[threadIdx.x] = pk(c, c);
    }
    __syncthreads();

    const int tp = 2 * (blockIdx.x * blockDim.x + threadIdx.x);
    if (tp >= TN) return;
    const int off = f*TN + tp;

    ull lm2[C8], ph2[C8];
    #pragma unroll
    for (int c = 0; c < C8; c++) {
        ull xr = ld64(x + ((b*2+0)*C8 + c)*CHW + off);
        ull xi = ld64(x + ((b*2+1)*C8 + c)*CHW + off);
        float r0, r1, i0, i1;
        upk(xr, r0, r1); upk(xi, i0, i1);
        float l0 = 0.5f * __logf(fmaf(r0, r0, fmaf(i0, i0, 1e-12f)));
        float l1 = 0.5f * __logf(fmaf(r1, r1, fmaf(i1, i1, 1e-12f)));
        lm2[c] = pk(l0, l1);
        ph2[c] = pk(atan2f(i0, r0), atan2f(i1, r1));
    }
    #pragma unroll
    for (int o = 0; o < C16; o++) {
        ull sr = sbr2[o], si = sbi2[o];
        #pragma unroll
        for (int c = 0; c < C8; c++) {
            sr = ffma2(swr2[o*C8+c], lm2[c], sr);
            si = ffma2(swi2[o*C8+c], ph2[c], si);
        }
        float s0, s1, p0, p1;
        upk(sr, s0, s1); upk(si, p0, p1);
        float w0 = (__cosf(p0) + 1.0f) * 0.5f;
        float w1 = (__cosf(p1) + 1.0f) * 0.5f;
        st64(g_s1 + ((b*2+0)*C16 + o)*CHW + off, pk(w0*s0, w1*s1));
        st64(g_s1 + ((b*2+1)*C16 + o)*CHW + off, pk(mod2pi(p0), mod2pi(p1)));
    }
}

// ---------------------------------------------------------------------------
// Kernel B: freq_conv (k=5, pad=2) -> cAct.  4 timesteps per thread,
// LDG.128 / STG.128 via ulonglong2, f32x2 math.
// ---------------------------------------------------------------------------
__global__ void kB(const float* __restrict__ wr, const float* __restrict__ wi,
                   const float* __restrict__ br, const float* __restrict__ bi)
{
    const int f  = blockIdx.y;
    const int bc = blockIdx.z;
    const int b  = bc / C16;
    const int c  = bc % C16;
    const int tp = 4 * (blockIdx.x * blockDim.x + threadIdx.x);
    if (tp >= TN) return;                     // TN % 4 == 0 -> no ragged tail

    const int base_r = ((b*2+0)*C16 + c)*CHW;
    const int base_i = ((b*2+1)*C16 + c)*CHW;

    float b_r = br[c], b_i = bi[c];
    ull yrL = pk(b_r, b_r), yrH = yrL;
    ull yiL = pk(b_i, b_i), yiH = yiL;
    #pragma unroll
    for (int j = 0; j < 5; j++) {
        int ff = f + j - 2;
        if (ff >= 0 && ff < FF) {
            float a = wr[c*5 + j]; float d = wi[c*5 + j];
            ull wa = pk(a, a), wd = pk(d, d);
            ulonglong2 vr = *reinterpret_cast<const ulonglong2*>(g_s1 + base_r + ff*TN + tp);
            ulonglong2 vi = *reinterpret_cast<const ulonglong2*>(g_s1 + base_i + ff*TN + tp);
            yrL = ffma2(wa, vr.x, yrL); yrH = ffma2(wa, vr.y, yrH);
            yiL = ffma2(wd, vi.x, yiL); yiH = ffma2(wd, vi.y, yiH);
        }
    }
    float r0, r1, r2, r3, i0, i1, i2, i3;
    upk(yrL, r0, r1); upk(yrH, r2, r3);
    upk(yiL, i0, i1); upk(yiH, i2, i3);
    float w0 = (__cosf(i0) + 1.0f) * 0.5f;
    float w1 = (__cosf(i1) + 1.0f) * 0.5f;
    float w2 = (__cosf(i2) + 1.0f) * 0.5f;
    float w3 = (__cosf(i3) + 1.0f) * 0.5f;
    ulonglong2 outr, outi;
    outr.x = pk(w0*r0, w1*r1); outr.y = pk(w2*r2, w3*r3);
    outi.x = pk(mod2pi(i0), mod2pi(i1)); outi.y = pk(mod2pi(i2), mod2pi(i3));
    *reinterpret_cast<ulonglong2*>(g_s2 + base_r + f*TN + tp) = outr;
    *reinterpret_cast<ulonglong2*>(g_s2 + base_i + f*TN + tp) = outi;
}

// ---------------------------------------------------------------------------
// Kernel C: 4 timesteps per thread.  time_conv taps via LDG.128 (3 float4
// per channel/ri), uniform LDS.128 weights, epilogue per half-pair with
// float2 stores.  launch_bounds(128,3) -> 170-reg cap (proven no-spill zone).
// ---------------------------------------------------------------------------
#define KC_THREADS 128
#define KC_TPT     4
#define KC_CHUNK   (KC_THREADS*KC_TPT)    // 512

__global__ void __launch_bounds__(KC_THREADS, 3) kC(
    const float* __restrict__ x,
    const float* __restrict__ twr, const float* __restrict__ twi,
    const float* __restrict__ tbr, const float* __restrict__ tbi,
    const float* __restrict__ lwr, const float* __restrict__ lwi,
    const float* __restrict__ lbr, const float* __restrict__ lbi,
    const float* __restrict__ awr, const float* __restrict__ awi,
    const float* __restrict__ abr, const float* __restrict__ abi,
    float* __restrict__ out)
{
    const int f     = blockIdx.y;
    const int b     = blockIdx.z;
    const int tBase = blockIdx.x * KC_CHUNK;

    __shared__ __align__(16) float stwr[C8*C16*5], stwi[C8*C16*5];  // [(c*5+k)*8+o]
    __shared__ float slwr[64], slwi[64], sawr[64], sawi[64];        // [o*8+c]
    __shared__ float stbr[8], stbi[8], slbr[8], slbi[8], sabr[8], sabi[8];

    for (int i = threadIdx.x; i < C8*C16*5; i += KC_THREADS) {
        int o = i & 7, ck = i >> 3;
        int c = ck / 5, k = ck - 5*c;
        stwr[i] = twr[f*C8*C16*5 + (o*C16 + c)*5 + k];
        stwi[i] = twi[f*C8*C16*5 + (o*C16 + c)*5 + k];
    }
    if (threadIdx.x < 64) {
        slwr[threadIdx.x] = lwr[f*64 + threadIdx.x];
        slwi[threadIdx.x] = lwi[f*64 + threadIdx.x];
        sawr[threadIdx.x] = awr[f*64 + threadIdx.x];
        sawi[threadIdx.x] = awi[f*64 + threadIdx.x];
    }
    if (threadIdx.x < 8) {
        stbr[threadIdx.x] = tbr[f*8 + threadIdx.x];
        stbi[threadIdx.x] = tbi[f*8 + threadIdx.x];
        slbr[threadIdx.x] = lbr[f*8 + threadIdx.x];
        slbi[threadIdx.x] = lbi[f*8 + threadIdx.x];
        sabr[threadIdx.x] = abr[f*8 + threadIdx.x];
        sabi[threadIdx.x] = abi[f*8 + threadIdx.x];
    }
    __syncthreads();

    const int t0 = tBase + KC_TPT*threadIdx.x;
    if (t0 >= TN) return;                       // TN%4==0 -> all 4 j valid

    const float* s2r  = g_s2 + (b*2+0)*C16*CHW + f*TN;
    const float* s2i  = g_s2 + (b*2+1)*C16*CHW + f*TN;
    const float* xr_p = x    + (b*2+0)*C8 *CHW + f*TN;
    const float* xi_p = x    + (b*2+1)*C8 *CHW + f*TN;
    float* outr = out + (b*2+0)*C8*CHW + f*TN;
    float* outi = out + (b*2+1)*C8*CHW + f*TN;

    // ---- time_conv: accumulate 8 outputs x 4 timesteps ----
    float ar[8][4], ai[8][4];
    #pragma unroll
    for (int o = 0; o < 8; o++) {
        #pragma unroll
        for (int j = 0; j < 4; j++) { ar[o][j] = stbr[o]; ai[o][j] = stbi[o]; }
    }

    const bool full = (t0 + 11 < TN);
    #pragma unroll
    for (int c = 0; c < C16; c++) {
        float vr[12], vi[12];
        if (full) {
            #pragma unroll
            for (int q = 0; q < 3; q++) {
                float4 a = *reinterpret_cast<const float4*>(s2r + c*CHW + t0 + 4*q);
                float4 d = *reinterpret_cast<const float4*>(s2i + c*CHW + t0 + 4*q);
                vr[4*q] = a.x; vr[4*q+1] = a.y; vr[4*q+2] = a.z; vr[4*q+3] = a.w;
                vi[4*q] = d.x; vi[4*q+1] = d.y; vi[4*q+2] = d.z; vi[4*q+3] = d.w;
            }
        } else {
            #pragma unroll
            for (int j = 0; j < 12; j++) {
                int tt = t0 + j;
                vr[j] = (tt < TN) ? s2r[c*CHW + tt] : 0.0f;
                vi[j] = (tt < TN) ? s2i[c*CHW + tt] : 0.0f;
            }
        }
        #pragma unroll
        for (int k = 0; k < 5; k++) {
            const float4 w0 = *reinterpret_cast<const float4*>(stwr + (c*5+k)*8);
            const float4 w1 = *reinterpret_cast<const float4*>(stwr + (c*5+k)*8 + 4);
            const float4 u0 = *reinterpret_cast<const float4*>(stwi + (c*5+k)*8);
            const float4 u1 = *reinterpret_cast<const float4*>(stwi + (c*5+k)*8 + 4);
            const float wrs[8] = {w0.x, w0.y, w0.z, w0.w, w1.x, w1.y, w1.z, w1.w};
            const float wis[8] = {u0.x, u0.y, u0.z, u0.w, u1.x, u1.y, u1.z, u1.w};
            #pragma unroll
            for (int o = 0; o < 8; o++) {
                #pragma unroll
                for (int j = 0; j < 4; j++) {
                    ar[o][j] = fmaf(wrs[o], vr[2*k+j], ar[o][j]);
                    ai[o][j] = fmaf(wis[o], vi[2*k+j], ai[o][j]);
                }
            }
        }
    }

    // ---- epilogue: two half-pairs, float2 stores ----
    #pragma unroll
    for (int jj = 0; jj < 2; jj++) {
        float orj[8][2], oij[8][2];
        #pragma unroll
        for (int j2 = 0; j2 < 2; j2++) {
            const int j = 2*jj + j2;
            // cExp
            float er[8], ei[8];
            #pragma unroll
            for (int o = 0; o < 8; o++) {
                float r = __expf(ar[o][j]);
                float sn, cs;
                __sincosf(ai[o][j], &sn, &cs);
                er[o] = r * cs;
                ei[o] = r * sn;
            }
            // last_shuffle (complex 8x8)
            float sr[8], si[8];
            #pragma unroll
            for (int o = 0; o < 8; o++) {
                float yr = slbr[o] - slbi[o];
                float yi = slbr[o] + slbi[o];
                #pragma unroll
                for (int c = 0; c < 8; c++) {
                    float wr_ = slwr[o*8+c], wi_ = slwi[o*8+c];
                    yr = fmaf(wr_, er[c], yr);
                    yr = fmaf(-wi_, ei[c], yr);
                    yi = fmaf(wr_, ei[c], yi);
                    yi = fmaf(wi_, er[c], yi);
                }
                sr[o] = yr; si[o] = yi;
            }
            // cMul with x
            #pragma unroll
            for (int c = 0; c < 8; c++) {
                float vxr = xr_p[c*CHW + t0 + j];
                float vxi = xi_p[c*CHW + t0 + j];
                float mr = sr[c]*vxr - si[c]*vxi;
                float mi = sr[c]*vxi + si[c]*vxr;
                sr[c] = mr; si[c] = mi;
            }
            // last (complex 8x8)
            #pragma unroll
            for (int o = 0; o < 8; o++) {
                float yr = sabr[o] - sabi[o];
                float yi = sabr[o] + sabi[o];
                #pragma unroll
                for (int c = 0; c < 8; c++) {
                    float wr_ = sawr[o*8+c], wi_ = sawi[o*8+c];
                    yr = fmaf(wr_, sr[c], yr);
                    yr = fmaf(-wi_, si[c], yr);
                    yi = fmaf(wr_, si[c], yi);
                    yi = fmaf(wi_, sr[c], yi);
                }
                orj[o][j2] = yr; oij[o][j2] = yi;
            }
        }
        #pragma unroll
        for (int o = 0; o < 8; o++) {
            *reinterpret_cast<float2*>(outr + o*CHW + t0 + 2*jj) = make_float2(orj[o][0], orj[o][1]);
            *reinterpret_cast<float2*>(outi + o*CHW + t0 + 2*jj) = make_float2(oij[o][0], oij[o][1]);
        }
    }
}

// ---------------------------------------------------------------------------
extern "C" void kernel_launch(void* const* d_in, const int* in_sizes, int n_in,
                              void* d_out, int out_size)
{
    const float* x     = (const float*)d_in[0];
    const float* cs_wr = (const float*)d_in[1];
    const float* cs_wi = (const float*)d_in[2];
    const float* cs_br = (const float*)d_in[3];
    const float* cs_bi = (const float*)d_in[4];
    const float* fc_wr = (const float*)d_in[5];
    const float* fc_wi = (const float*)d_in[6];
    const float* fc_br = (const float*)d_in[7];
    const float* fc_bi = (const float*)d_in[8];
    const float* tc_wr = (const float*)d_in[9];
    const float* tc_wi = (const float*)d_in[10];
    const float* tc_br = (const float*)d_in[11];
    const float* tc_bi = (const float*)d_in[12];
    const float* ls_wr = (const float*)d_in[13];
    const float* ls_wi = (const float*)d_in[14];
    const float* ls_br = (const float*)d_in[15];
    const float* ls_bi = (const float*)d_in[16];
    const float* la_wr = (const float*)d_in[17];
    const float* la_wi = (const float*)d_in[18];
    const float* la_br = (const float*)d_in[19];
    const float* la_bi = (const float*)d_in[20];
    float* out = (float*)d_out;

    dim3 gA((TN/2 + 255)/256, FF, BB);
    kA<<<gA, 256>>>(x, cs_wr, cs_wi, cs_br, cs_bi);

    dim3 gB((TN/4 + 255)/256, FF, BB*C16);
    kB<<<gB, 256>>>(fc_wr, fc_wi, fc_br, fc_bi);

    dim3 gC((TN + KC_CHUNK - 1)/KC_CHUNK, FF, BB);   // 4, 256, 4
    kC<<<gC, KC_THREADS>>>(x, tc_wr, tc_wi, tc_br, tc_bi,
                           ls_wr, ls_wi, ls_br, ls_bi,
                           la_wr, la_wi, la_br, la_bi, out);
}

// round 12
// speedup vs baseline: 1.7882x; 1.5622x over previous
#include <cuda_runtime.h>
#include <math.h>

#define BB   4
#define C8   8
#define C16  16
#define FF   256
#define TN   2000
#define CHW  (FF*TN)
#define TWO_PI_F     6.283185307179586f
#define INV_TWO_PI_F 0.15915494309189535f

typedef unsigned long long ull;

__device__ float g_s1[BB*2*C16*CHW];
__device__ float g_s2[BB*2*C16*CHW];

__device__ __forceinline__ float mod2pi(float a) {
    return a - floorf(a * INV_TWO_PI_F) * TWO_PI_F;
}

// ---- f32x2 helpers (kA/kB only) ----
__device__ __forceinline__ ull pk(float lo, float hi) {
    ull r; asm("mov.b64 %0,{%1,%2};" : "=l"(r) : "f"(lo), "f"(hi)); return r;
}
__device__ __forceinline__ void upk(ull v, float& lo, float& hi) {
    asm("mov.b64 {%0,%1},%2;" : "=f"(lo), "=f"(hi) : "l"(v));
}
__device__ __forceinline__ ull ffma2(ull a, ull b, ull c) {
    ull d; asm("fma.rn.f32x2 %0,%1,%2,%3;" : "=l"(d) : "l"(a), "l"(b), "l"(c)); return d;
}
__device__ __forceinline__ ull ld64(const float* p) {
    return *reinterpret_cast<const ull*>(p);
}
__device__ __forceinline__ void st64(float* p, ull v) {
    *reinterpret_cast<ull*>(p) = v;
}

// ---------------------------------------------------------------------------
// Kernel A: cLog -> channel_shuffle (8->16) -> cAct.  2 timesteps per thread.
// (measured ~105 us, stable — unchanged)
// ---------------------------------------------------------------------------
__global__ void kA(const float* __restrict__ x,
                   const float* __restrict__ wr, const float* __restrict__ wi,
                   const float* __restrict__ br, const float* __restrict__ bi)
{
    const int f = blockIdx.y;
    const int b = blockIdx.z;

    __shared__ ull swr2[C16*C8], swi2[C16*C8];
    __shared__ ull sbr2[C16], sbi2[C16];
    for (int i = threadIdx.x; i < C16*C8; i += blockDim.x) {
        float a = wr[f*C16*C8 + i]; swr2[i] = pk(a, a);
        float c = wi[f*C16*C8 + i]; swi2[i] = pk(c, c);
    }
    if (threadIdx.x < C16) {
        float a = br[f*C16 + threadIdx.x]; sbr2[threadIdx.x] = pk(a, a);
        float c = bi[f*C16 + threadIdx.x]; sbi2[threadIdx.x] = pk(c, c);
    }
    __syncthreads();

    const int tp = 2 * (blockIdx.x * blockDim.x + threadIdx.x);
    if (tp >= TN) return;
    const int off = f*TN + tp;

    ull lm2[C8], ph2[C8];
    #pragma unroll
    for (int c = 0; c < C8; c++) {
        ull xr = ld64(x + ((b*2+0)*C8 + c)*CHW + off);
        ull xi = ld64(x + ((b*2+1)*C8 + c)*CHW + off);
        float r0, r1, i0, i1;
        upk(xr, r0, r1); upk(xi, i0, i1);
        float l0 = 0.5f * __logf(fmaf(r0, r0, fmaf(i0, i0, 1e-12f)));
        float l1 = 0.5f * __logf(fmaf(r1, r1, fmaf(i1, i1, 1e-12f)));
        lm2[c] = pk(l0, l1);
        ph2[c] = pk(atan2f(i0, r0), atan2f(i1, r1));
    }
    #pragma unroll
    for (int o = 0; o < C16; o++) {
        ull sr = sbr2[o], si = sbi2[o];
        #pragma unroll
        for (int c = 0; c < C8; c++) {
            sr = ffma2(swr2[o*C8+c], lm2[c], sr);
            si = ffma2(swi2[o*C8+c], ph2[c], si);
        }
        float s0, s1, p0, p1;
        upk(sr, s0, s1); upk(si, p0, p1);
        float w0 = (__cosf(p0) + 1.0f) * 0.5f;
        float w1 = (__cosf(p1) + 1.0f) * 0.5f;
        st64(g_s1 + ((b*2+0)*C16 + o)*CHW + off, pk(w0*s0, w1*s1));
        st64(g_s1 + ((b*2+1)*C16 + o)*CHW + off, pk(mod2pi(p0), mod2pi(p1)));
    }
}

// ---------------------------------------------------------------------------
// Kernel B: freq_conv (depthwise over freq, k=5, pad=2) -> cAct. 2 t/thread.
// (R9 version, ~130 us)
// ---------------------------------------------------------------------------
__global__ void kB(const float* __restrict__ wr, const float* __restrict__ wi,
                   const float* __restrict__ br, const float* __restrict__ bi)
{
    const int f  = blockIdx.y;
    const int bc = blockIdx.z;
    const int b  = bc / C16;
    const int c  = bc % C16;
    const int tp = 2 * (blockIdx.x * blockDim.x + threadIdx.x);
    if (tp >= TN) return;

    const int base_r = ((b*2+0)*C16 + c)*CHW;
    const int base_i = ((b*2+1)*C16 + c)*CHW;

    float b_r = br[c], b_i = bi[c];
    ull yr = pk(b_r, b_r);
    ull yi = pk(b_i, b_i);
    #pragma unroll
    for (int j = 0; j < 5; j++) {
        int ff = f + j - 2;
        if (ff >= 0 && ff < FF) {
            float a = wr[c*5 + j]; float d = wi[c*5 + j];
            yr = ffma2(pk(a, a), ld64(g_s1 + base_r + ff*TN + tp), yr);
            yi = ffma2(pk(d, d), ld64(g_s1 + base_i + ff*TN + tp), yi);
        }
    }
    float r0, r1, i0, i1;
    upk(yr, r0, r1); upk(yi, i0, i1);
    float w0 = (__cosf(i0) + 1.0f) * 0.5f;
    float w1 = (__cosf(i1) + 1.0f) * 0.5f;
    st64(g_s2 + base_r + f*TN + tp, pk(w0*r0, w1*r1));
    st64(g_s2 + base_i + f*TN + tp, pk(mod2pi(i0), mod2pi(i1)));
}

// ---------------------------------------------------------------------------
// Kernel C: per block (256-t chunk, f, b):
//   phase 1: cooperative COPY (no compute) of s2 tile -> SMEM, zero-filled
//   phase 2: one t-pair/thread, R9 epilogue with taps from LDS (29 cyc)
// launch_bounds(128,3): 170-reg cap (proven no-spill for this body).
// ---------------------------------------------------------------------------
#define KC_THREADS 128
#define TC2    256
#define T_PAD  272                      // 68 float4 per plane; covers 265 needed
#define NQ     (T_PAD/4)                // 68

__global__ void __launch_bounds__(KC_THREADS, 3) kC(
    const float* __restrict__ x,
    const float* __restrict__ twr, const float* __restrict__ twi,
    const float* __restrict__ tbr, const float* __restrict__ tbi,
    const float* __restrict__ lwr, const float* __restrict__ lwi,
    const float* __restrict__ lbr, const float* __restrict__ lbi,
    const float* __restrict__ awr, const float* __restrict__ awi,
    const float* __restrict__ abr, const float* __restrict__ abi,
    float* __restrict__ out)
{
    const int f     = blockIdx.y;
    const int b     = blockIdx.z;
    const int tBase = blockIdx.x * TC2;
    const int tid   = threadIdx.x;

    __shared__ __align__(16) float s2t[32*T_PAD];                   // [(c*2+ri)*T_PAD + tl]
    __shared__ __align__(16) float stwr[C8*C16*5], stwi[C8*C16*5];  // [(c*5+k)*8+o]
    __shared__ float slwr[64], slwi[64], sawr[64], sawi[64];        // [o*8+c]
    __shared__ float stbr[8], stbi[8], slbr[8], slbi[8], sabr[8], sabi[8];

    // ---- stage weights ----
    for (int i = tid; i < C8*C16*5; i += KC_THREADS) {
        int o = i & 7, ck = i >> 3;
        int c = ck / 5, k = ck - 5*c;
        stwr[i] = twr[f*C8*C16*5 + (o*C16 + c)*5 + k];
        stwi[i] = twi[f*C8*C16*5 + (o*C16 + c)*5 + k];
    }
    if (tid < 64) {
        slwr[tid] = lwr[f*64 + tid];
        slwi[tid] = lwi[f*64 + tid];
        sawr[tid] = awr[f*64 + tid];
        sawi[tid] = awi[f*64 + tid];
    }
    if (tid < 8) {
        stbr[tid] = tbr[f*8 + tid];
        stbi[tid] = tbi[f*8 + tid];
        slbr[tid] = lbr[f*8 + tid];
        slbi[tid] = lbi[f*8 + tid];
        sabr[tid] = abr[f*8 + tid];
        sabi[tid] = abi[f*8 + tid];
    }

    // ---- phase 1: cooperative copy g_s2 tile -> smem (zero-fill past TN) ----
    for (int i = tid; i < 32*NQ; i += KC_THREADS) {
        const int pl = i / NQ;              // 0..31
        const int q  = i - pl*NQ;           // 0..67
        const int c  = pl >> 1, ri = pl & 1;
        const float* gp = g_s2 + ((b*2+ri)*C16 + c)*CHW + f*TN;
        const int tt = tBase + 4*q;
        float4 v;
        if (tt + 3 < TN) {
            v = *reinterpret_cast<const float4*>(gp + tt);
        } else {
            v.x = (tt     < TN) ? gp[tt]     : 0.0f;
            v.y = (tt + 1 < TN) ? gp[tt + 1] : 0.0f;
            v.z = (tt + 2 < TN) ? gp[tt + 2] : 0.0f;
            v.w = (tt + 3 < TN) ? gp[tt + 3] : 0.0f;
        }
        *reinterpret_cast<float4*>(&s2t[pl*T_PAD + 4*q]) = v;
    }
    __syncthreads();

    // ---- phase 2: one t-pair per thread ----
    const int tl0 = 2*tid;
    const int t0  = tBase + tl0;
    if (t0 >= TN) return;

    const float* xr_p = x + (b*2+0)*C8*CHW + f*TN;
    const float* xi_p = x + (b*2+1)*C8*CHW + f*TN;
    float* outr = out + (b*2+0)*C8*CHW + f*TN;
    float* outi = out + (b*2+1)*C8*CHW + f*TN;

    float ar[8][2], ai[8][2];
    #pragma unroll
    for (int o = 0; o < 8; o++) {
        ar[o][0] = stbr[o]; ar[o][1] = stbr[o];
        ai[o][0] = stbi[o]; ai[o][1] = stbi[o];
    }

    #pragma unroll
    for (int c = 0; c < C16; c++) {
        float vr[10], vi[10];
        #pragma unroll
        for (int m = 0; m < 5; m++) {
            float2 a = *reinterpret_cast<const float2*>(&s2t[(c*2+0)*T_PAD + tl0 + 2*m]);
            float2 d = *reinterpret_cast<const float2*>(&s2t[(c*2+1)*T_PAD + tl0 + 2*m]);
            vr[2*m] = a.x; vr[2*m+1] = a.y;
            vi[2*m] = d.x; vi[2*m+1] = d.y;
        }
        #pragma unroll
        for (int k = 0; k < 5; k++) {
            const float4 w0 = *reinterpret_cast<const float4*>(stwr + (c*5+k)*8);
            const float4 w1 = *reinterpret_cast<const float4*>(stwr + (c*5+k)*8 + 4);
            const float4 u0 = *reinterpret_cast<const float4*>(stwi + (c*5+k)*8);
            const float4 u1 = *reinterpret_cast<const float4*>(stwi + (c*5+k)*8 + 4);
            const float wrs[8] = {w0.x, w0.y, w0.z, w0.w, w1.x, w1.y, w1.z, w1.w};
            const float wis[8] = {u0.x, u0.y, u0.z, u0.w, u1.x, u1.y, u1.z, u1.w};
            #pragma unroll
            for (int o = 0; o < 8; o++) {
                ar[o][0] = fmaf(wrs[o], vr[2*k],   ar[o][0]);
                ar[o][1] = fmaf(wrs[o], vr[2*k+1], ar[o][1]);
                ai[o][0] = fmaf(wis[o], vi[2*k],   ai[o][0]);
                ai[o][1] = fmaf(wis[o], vi[2*k+1], ai[o][1]);
            }
        }
    }

    float orj[8][2], oij[8][2];
    #pragma unroll
    for (int j = 0; j < 2; j++) {
        // cExp
        float er[8], ei[8];
        #pragma unroll
        for (int o = 0; o < 8; o++) {
            float r = __expf(ar[o][j]);
            float sn, cs;
            __sincosf(ai[o][j], &sn, &cs);
            er[o] = r * cs;
            ei[o] = r * sn;
        }
        // last_shuffle (complex 8x8)
        float sr[8], si[8];
        #pragma unroll
        for (int o = 0; o < 8; o++) {
            float yr = slbr[o] - slbi[o];
            float yi = slbr[o] + slbi[o];
            #pragma unroll
            for (int c = 0; c < 8; c++) {
                float wr_ = slwr[o*8+c], wi_ = slwi[o*8+c];
                yr = fmaf(wr_, er[c], yr);
                yr = fmaf(-wi_, ei[c], yr);
                yi = fmaf(wr_, ei[c], yi);
                yi = fmaf(wi_, er[c], yi);
            }
            sr[o] = yr; si[o] = yi;
        }
        // cMul with x
        #pragma unroll
        for (int c = 0; c < 8; c++) {
            float vxr = xr_p[c*CHW + t0 + j];
            float vxi = xi_p[c*CHW + t0 + j];
            float mr = sr[c]*vxr - si[c]*vxi;
            float mi = sr[c]*vxi + si[c]*vxr;
            sr[c] = mr; si[c] = mi;
        }
        // last (complex 8x8)
        #pragma unroll
        for (int o = 0; o < 8; o++) {
            float yr = sabr[o] - sabi[o];
            float yi = sabr[o] + sabi[o];
            #pragma unroll
            for (int c = 0; c < 8; c++) {
                float wr_ = sawr[o*8+c], wi_ = sawi[o*8+c];
                yr = fmaf(wr_, sr[c], yr);
                yr = fmaf(-wi_, si[c], yr);
                yi = fmaf(wr_, si[c], yi);
                yi = fmaf(wi_, sr[c], yi);
            }
            orj[o][j] = yr; oij[o][j] = yi;
        }
    }
    #pragma unroll
    for (int o = 0; o < 8; o++) {
        *reinterpret_cast<float2*>(outr + o*CHW + t0) = make_float2(orj[o][0], orj[o][1]);
        *reinterpret_cast<float2*>(outi + o*CHW + t0) = make_float2(oij[o][0], oij[o][1]);
    }
}

// ---------------------------------------------------------------------------
extern "C" void kernel_launch(void* const* d_in, const int* in_sizes, int n_in,
                              void* d_out, int out_size)
{
    const float* x     = (const float*)d_in[0];
    const float* cs_wr = (const float*)d_in[1];
    const float* cs_wi = (const float*)d_in[2];
    const float* cs_br = (const float*)d_in[3];
    const float* cs_bi = (const float*)d_in[4];
    const float* fc_wr = (const float*)d_in[5];
    const float* fc_wi = (const float*)d_in[6];
    const float* fc_br = (const float*)d_in[7];
    const float* fc_bi = (const float*)d_in[8];
    const float* tc_wr = (const float*)d_in[9];
    const float* tc_wi = (const float*)d_in[10];
    const float* tc_br = (const float*)d_in[11];
    const float* tc_bi = (const float*)d_in[12];
    const float* ls_wr = (const float*)d_in[13];
    const float* ls_wi = (const float*)d_in[14];
    const float* ls_br = (const float*)d_in[15];
    const float* ls_bi = (const float*)d_in[16];
    const float* la_wr = (const float*)d_in[17];
    const float* la_wi = (const float*)d_in[18];
    const float* la_br = (const float*)d_in[19];
    const float* la_bi = (const float*)d_in[20];
    float* out = (float*)d_out;

    dim3 gA((TN/2 + 255)/256, FF, BB);
    kA<<<gA, 256>>>(x, cs_wr, cs_wi, cs_br, cs_bi);

    dim3 gB((TN/2 + 255)/256, FF, BB*C16);
    kB<<<gB, 256>>>(fc_wr, fc_wi, fc_br, fc_bi);

    dim3 gC((TN + TC2 - 1)/TC2, FF, BB);   // 8, 256, 4
    kC<<<gC, KC_THREADS>>>(x, tc_wr, tc_wi, tc_br, tc_bi,
                           ls_wr, ls_wi, ls_br, ls_bi,
                           la_wr, la_wi, la_br, la_bi, out);
}

// round 13
// speedup vs baseline: 2.1754x; 1.2165x over previous
#include <cuda_runtime.h>
#include <math.h>

#define BB   4
#define C8   8
#define C16  16
#define FF   256
#define TN   2000
#define CHW  (FF*TN)
#define TWO_PI_F     6.283185307179586f
#define INV_TWO_PI_F 0.15915494309189535f

typedef unsigned long long ull;

__device__ float g_s1[BB*2*C16*CHW];
__device__ float g_s2[BB*2*C16*CHW];

__device__ __forceinline__ float mod2pi(float a) {
    return a - floorf(a * INV_TWO_PI_F) * TWO_PI_F;
}

// ---- f32x2 helpers (kA/kB only) ----
__device__ __forceinline__ ull pk(float lo, float hi) {
    ull r; asm("mov.b64 %0,{%1,%2};" : "=l"(r) : "f"(lo), "f"(hi)); return r;
}
__device__ __forceinline__ void upk(ull v, float& lo, float& hi) {
    asm("mov.b64 {%0,%1},%2;" : "=f"(lo), "=f"(hi) : "l"(v));
}
__device__ __forceinline__ ull ffma2(ull a, ull b, ull c) {
    ull d; asm("fma.rn.f32x2 %0,%1,%2,%3;" : "=l"(d) : "l"(a), "l"(b), "l"(c)); return d;
}
__device__ __forceinline__ ull ld64(const float* p) {
    return *reinterpret_cast<const ull*>(p);
}
__device__ __forceinline__ void st64(float* p, ull v) {
    *reinterpret_cast<ull*>(p) = v;
}

// ---------------------------------------------------------------------------
// Kernel A: cLog -> channel_shuffle (8->16) -> cAct.  4 timesteps per thread,
// LDG.128 / STG.128, f32x2 matmul.
// ---------------------------------------------------------------------------
__global__ void kA(const float* __restrict__ x,
                   const float* __restrict__ wr, const float* __restrict__ wi,
                   const float* __restrict__ br, const float* __restrict__ bi)
{
    const int f = blockIdx.y;
    const int b = blockIdx.z;

    __shared__ ull swr2[C16*C8], swi2[C16*C8];
    __shared__ ull sbr2[C16], sbi2[C16];
    for (int i = threadIdx.x; i < C16*C8; i += blockDim.x) {
        float a = wr[f*C16*C8 + i]; swr2[i] = pk(a, a);
        float c = wi[f*C16*C8 + i]; swi2[i] = pk(c, c);
    }
    if (threadIdx.x < C16) {
        float a = br[f*C16 + threadIdx.x]; sbr2[threadIdx.x] = pk(a, a);
        float c = bi[f*C16 + threadIdx.x]; sbi2[threadIdx.x] = pk(c, c);
    }
    __syncthreads();

    const int tp = 4 * (blockIdx.x * blockDim.x + threadIdx.x);
    if (tp >= TN) return;                 // TN % 4 == 0
    const int off = f*TN + tp;

    ull lmL[C8], lmH[C8], phL[C8], phH[C8];
    #pragma unroll
    for (int c = 0; c < C8; c++) {
        ulonglong2 xr = *reinterpret_cast<const ulonglong2*>(x + ((b*2+0)*C8 + c)*CHW + off);
        ulonglong2 xi = *reinterpret_cast<const ulonglong2*>(x + ((b*2+1)*C8 + c)*CHW + off);
        float r0, r1, r2, r3, i0, i1, i2, i3;
        upk(xr.x, r0, r1); upk(xr.y, r2, r3);
        upk(xi.x, i0, i1); upk(xi.y, i2, i3);
        float l0 = 0.5f * __logf(fmaf(r0, r0, fmaf(i0, i0, 1e-12f)));
        float l1 = 0.5f * __logf(fmaf(r1, r1, fmaf(i1, i1, 1e-12f)));
        float l2 = 0.5f * __logf(fmaf(r2, r2, fmaf(i2, i2, 1e-12f)));
        float l3 = 0.5f * __logf(fmaf(r3, r3, fmaf(i3, i3, 1e-12f)));
        lmL[c] = pk(l0, l1); lmH[c] = pk(l2, l3);
        phL[c] = pk(atan2f(i0, r0), atan2f(i1, r1));
        phH[c] = pk(atan2f(i2, r2), atan2f(i3, r3));
    }
    #pragma unroll
    for (int o = 0; o < C16; o++) {
        ull srL = sbr2[o], srH = srL;
        ull siL = sbi2[o], siH = siL;
        #pragma unroll
        for (int c = 0; c < C8; c++) {
            ull wr_ = swr2[o*C8+c], wi_ = swi2[o*C8+c];
            srL = ffma2(wr_, lmL[c], srL); srH = ffma2(wr_, lmH[c], srH);
            siL = ffma2(wi_, phL[c], siL); siH = ffma2(wi_, phH[c], siH);
        }
        float s0, s1, s2, s3, p0, p1, p2, p3;
        upk(srL, s0, s1); upk(srH, s2, s3);
        upk(siL, p0, p1); upk(siH, p2, p3);
        float w0 = (__cosf(p0) + 1.0f) * 0.5f;
        float w1 = (__cosf(p1) + 1.0f) * 0.5f;
        float w2 = (__cosf(p2) + 1.0f) * 0.5f;
        float w3 = (__cosf(p3) + 1.0f) * 0.5f;
        ulonglong2 outr, outi;
        outr.x = pk(w0*s0, w1*s1); outr.y = pk(w2*s2, w3*s3);
        outi.x = pk(mod2pi(p0), mod2pi(p1)); outi.y = pk(mod2pi(p2), mod2pi(p3));
        *reinterpret_cast<ulonglong2*>(g_s1 + ((b*2+0)*C16 + o)*CHW + off) = outr;
        *reinterpret_cast<ulonglong2*>(g_s1 + ((b*2+1)*C16 + o)*CHW + off) = outi;
    }
}

// ---------------------------------------------------------------------------
// Kernel B: freq_conv (k=5, pad=2) -> cAct.  4 timesteps per thread,
// LDG.128 / STG.128 via ulonglong2, f32x2 math.  (R11 version — proven.)
// ---------------------------------------------------------------------------
__global__ void kB(const float* __restrict__ wr, const float* __restrict__ wi,
                   const float* __restrict__ br, const float* __restrict__ bi)
{
    const int f  = blockIdx.y;
    const int bc = blockIdx.z;
    const int b  = bc / C16;
    const int c  = bc % C16;
    const int tp = 4 * (blockIdx.x * blockDim.x + threadIdx.x);
    if (tp >= TN) return;

    const int base_r = ((b*2+0)*C16 + c)*CHW;
    const int base_i = ((b*2+1)*C16 + c)*CHW;

    float b_r = br[c], b_i = bi[c];
    ull yrL = pk(b_r, b_r), yrH = yrL;
    ull yiL = pk(b_i, b_i), yiH = yiL;
    #pragma unroll
    for (int j = 0; j < 5; j++) {
        int ff = f + j - 2;
        if (ff >= 0 && ff < FF) {
            float a = wr[c*5 + j]; float d = wi[c*5 + j];
            ull wa = pk(a, a), wd = pk(d, d);
            ulonglong2 vr = *reinterpret_cast<const ulonglong2*>(g_s1 + base_r + ff*TN + tp);
            ulonglong2 vi = *reinterpret_cast<const ulonglong2*>(g_s1 + base_i + ff*TN + tp);
            yrL = ffma2(wa, vr.x, yrL); yrH = ffma2(wa, vr.y, yrH);
            yiL = ffma2(wd, vi.x, yiL); yiH = ffma2(wd, vi.y, yiH);
        }
    }
    float r0, r1, r2, r3, i0, i1, i2, i3;
    upk(yrL, r0, r1); upk(yrH, r2, r3);
    upk(yiL, i0, i1); upk(yiH, i2, i3);
    float w0 = (__cosf(i0) + 1.0f) * 0.5f;
    float w1 = (__cosf(i1) + 1.0f) * 0.5f;
    float w2 = (__cosf(i2) + 1.0f) * 0.5f;
    float w3 = (__cosf(i3) + 1.0f) * 0.5f;
    ulonglong2 outr, outi;
    outr.x = pk(w0*r0, w1*r1); outr.y = pk(w2*r2, w3*r3);
    outi.x = pk(mod2pi(i0), mod2pi(i1)); outi.y = pk(mod2pi(i2), mod2pi(i3));
    *reinterpret_cast<ulonglong2*>(g_s2 + base_r + f*TN + tp) = outr;
    *reinterpret_cast<ulonglong2*>(g_s2 + base_i + f*TN + tp) = outi;
}

// ---------------------------------------------------------------------------
// Kernel C: R9 champion version, UNCHANGED.  2 t/thread, float2 LDG taps,
// uniform LDS.128 weights, launch_bounds(128,3), t-range split in half.
// ---------------------------------------------------------------------------
#define KC_THREADS 128
#define KC_TSPLIT  2
#define KC_TLEN    (TN / KC_TSPLIT)      // 1000

template<bool FULL>
__device__ __forceinline__ void tc_core(
    const float* __restrict__ s2r, const float* __restrict__ s2i,
    const float* __restrict__ stwr, const float* __restrict__ stwi,
    int t0, float ar[8][2], float ai[8][2])
{
    #pragma unroll
    for (int c = 0; c < C16; c++) {
        float vr[10], vi[10];
        if (FULL) {
            #pragma unroll
            for (int m = 0; m < 5; m++) {
                float2 a = *reinterpret_cast<const float2*>(s2r + c*CHW + t0 + 2*m);
                float2 d = *reinterpret_cast<const float2*>(s2i + c*CHW + t0 + 2*m);
                vr[2*m] = a.x; vr[2*m+1] = a.y;
                vi[2*m] = d.x; vi[2*m+1] = d.y;
            }
        } else {
            #pragma unroll
            for (int j = 0; j < 10; j++) {
                int tt = t0 + j;
                vr[j] = (tt < TN) ? s2r[c*CHW + tt] : 0.0f;
                vi[j] = (tt < TN) ? s2i[c*CHW + tt] : 0.0f;
            }
        }
        #pragma unroll
        for (int k = 0; k < 5; k++) {
            const float4 w0 = *reinterpret_cast<const float4*>(stwr + (c*5+k)*8);
            const float4 w1 = *reinterpret_cast<const float4*>(stwr + (c*5+k)*8 + 4);
            const float4 u0 = *reinterpret_cast<const float4*>(stwi + (c*5+k)*8);
            const float4 u1 = *reinterpret_cast<const float4*>(stwi + (c*5+k)*8 + 4);
            const float wrs[8] = {w0.x, w0.y, w0.z, w0.w, w1.x, w1.y, w1.z, w1.w};
            const float wis[8] = {u0.x, u0.y, u0.z, u0.w, u1.x, u1.y, u1.z, u1.w};
            #pragma unroll
            for (int o = 0; o < 8; o++) {
                ar[o][0] = fmaf(wrs[o], vr[2*k],   ar[o][0]);
                ar[o][1] = fmaf(wrs[o], vr[2*k+1], ar[o][1]);
                ai[o][0] = fmaf(wis[o], vi[2*k],   ai[o][0]);
                ai[o][1] = fmaf(wis[o], vi[2*k+1], ai[o][1]);
            }
        }
    }
}

__global__ void __launch_bounds__(KC_THREADS, 3) kC(
    const float* __restrict__ x,
    const float* __restrict__ twr, const float* __restrict__ twi,
    const float* __restrict__ tbr, const float* __restrict__ tbi,
    const float* __restrict__ lwr, const float* __restrict__ lwi,
    const float* __restrict__ lbr, const float* __restrict__ lbi,
    const float* __restrict__ awr, const float* __restrict__ awi,
    const float* __restrict__ abr, const float* __restrict__ abi,
    float* __restrict__ out)
{
    const int f    = blockIdx.x & (FF-1);
    const int bh   = blockIdx.x >> 8;
    const int b    = bh >> 1;               // batch
    const int half = bh & 1;                // t-range half
    const int tBeg = half * KC_TLEN;
    const int tEnd = tBeg + KC_TLEN;

    __shared__ __align__(16) float stwr[C8*C16*5], stwi[C8*C16*5];  // [(c*5+k)*8+o]
    __shared__ float slwr[64], slwi[64], sawr[64], sawi[64];        // [o*8+c]
    __shared__ float stbr[8], stbi[8], slbr[8], slbi[8], sabr[8], sabi[8];

    for (int i = threadIdx.x; i < C8*C16*5; i += KC_THREADS) {
        int o = i & 7, ck = i >> 3;
        int c = ck / 5, k = ck - 5*c;
        stwr[i] = twr[f*C8*C16*5 + (o*C16 + c)*5 + k];
        stwi[i] = twi[f*C8*C16*5 + (o*C16 + c)*5 + k];
    }
    if (threadIdx.x < 64) {
        slwr[threadIdx.x] = lwr[f*64 + threadIdx.x];
        slwi[threadIdx.x] = lwi[f*64 + threadIdx.x];
        sawr[threadIdx.x] = awr[f*64 + threadIdx.x];
        sawi[threadIdx.x] = awi[f*64 + threadIdx.x];
    }
    if (threadIdx.x < 8) {
        stbr[threadIdx.x] = tbr[f*8 + threadIdx.x];
        stbi[threadIdx.x] = tbi[f*8 + threadIdx.x];
        slbr[threadIdx.x] = lbr[f*8 + threadIdx.x];
        slbi[threadIdx.x] = lbi[f*8 + threadIdx.x];
        sabr[threadIdx.x] = abr[f*8 + threadIdx.x];
        sabi[threadIdx.x] = abi[f*8 + threadIdx.x];
    }
    __syncthreads();

    const float* s2r  = g_s2 + (b*2+0)*C16*CHW + f*TN;
    const float* s2i  = g_s2 + (b*2+1)*C16*CHW + f*TN;
    const float* xr_p = x    + (b*2+0)*C8 *CHW + f*TN;
    const float* xi_p = x    + (b*2+1)*C8 *CHW + f*TN;
    float* outr = out + (b*2+0)*C8*CHW + f*TN;
    float* outi = out + (b*2+1)*C8*CHW + f*TN;

    for (int t0 = tBeg + 2*threadIdx.x; t0 < tEnd; t0 += 2*KC_THREADS) {
        float ar[8][2], ai[8][2];
        #pragma unroll
        for (int o = 0; o < 8; o++) {
            ar[o][0] = stbr[o]; ar[o][1] = stbr[o];
            ai[o][0] = stbi[o]; ai[o][1] = stbi[o];
        }

        if (t0 + 9 < TN) tc_core<true >(s2r, s2i, stwr, stwi, t0, ar, ai);
        else             tc_core<false>(s2r, s2i, stwr, stwi, t0, ar, ai);

        float orj[8][2], oij[8][2];
        #pragma unroll
        for (int j = 0; j < 2; j++) {
            // cExp
            float er[8], ei[8];
            #pragma unroll
            for (int o = 0; o < 8; o++) {
                float r = __expf(ar[o][j]);
                float sn, cs;
                __sincosf(ai[o][j], &sn, &cs);
                er[o] = r * cs;
                ei[o] = r * sn;
            }
            // last_shuffle (complex 8x8)
            float sr[8], si[8];
            #pragma unroll
            for (int o = 0; o < 8; o++) {
                float yr = slbr[o] - slbi[o];
                float yi = slbr[o] + slbi[o];
                #pragma unroll
                for (int c = 0; c < 8; c++) {
                    float wr_ = slwr[o*8+c], wi_ = slwi[o*8+c];
                    yr = fmaf(wr_, er[c], yr);
                    yr = fmaf(-wi_, ei[c], yr);
                    yi = fmaf(wr_, ei[c], yi);
                    yi = fmaf(wi_, er[c], yi);
                }
                sr[o] = yr; si[o] = yi;
            }
            // cMul with x (in place)
            #pragma unroll
            for (int c = 0; c < 8; c++) {
                float vxr = xr_p[c*CHW + t0 + j];
                float vxi = xi_p[c*CHW + t0 + j];
                float mr = sr[c]*vxr - si[c]*vxi;
                float mi = sr[c]*vxi + si[c]*vxr;
                sr[c] = mr; si[c] = mi;
            }
            // last (complex 8x8)
            #pragma unroll
            for (int o = 0; o < 8; o++) {
                float yr = sabr[o] - sabi[o];
                float yi = sabr[o] + sabi[o];
                #pragma unroll
                for (int c = 0; c < 8; c++) {
                    float wr_ = sawr[o*8+c], wi_ = sawi[o*8+c];
                    yr = fmaf(wr_, sr[c], yr);
                    yr = fmaf(-wi_, si[c], yr);
                    yi = fmaf(wr_, si[c], yi);
                    yi = fmaf(wi_, sr[c], yi);
                }
                orj[o][j] = yr; oij[o][j] = yi;
            }
        }
        #pragma unroll
        for (int o = 0; o < 8; o++) {
            *reinterpret_cast<float2*>(outr + o*CHW + t0) = make_float2(orj[o][0], orj[o][1]);
            *reinterpret_cast<float2*>(outi + o*CHW + t0) = make_float2(oij[o][0], oij[o][1]);
        }
    }
}

// ---------------------------------------------------------------------------
extern "C" void kernel_launch(void* const* d_in, const int* in_sizes, int n_in,
                              void* d_out, int out_size)
{
    const float* x     = (const float*)d_in[0];
    const float* cs_wr = (const float*)d_in[1];
    const float* cs_wi = (const float*)d_in[2];
    const float* cs_br = (const float*)d_in[3];
    const float* cs_bi = (const float*)d_in[4];
    const float* fc_wr = (const float*)d_in[5];
    const float* fc_wi = (const float*)d_in[6];
    const float* fc_br = (const float*)d_in[7];
    const float* fc_bi = (const float*)d_in[8];
    const float* tc_wr = (const float*)d_in[9];
    const float* tc_wi = (const float*)d_in[10];
    const float* tc_br = (const float*)d_in[11];
    const float* tc_bi = (const float*)d_in[12];
    const float* ls_wr = (const float*)d_in[13];
    const float* ls_wi = (const float*)d_in[14];
    const float* ls_br = (const float*)d_in[15];
    const float* ls_bi = (const float*)d_in[16];
    const float* la_wr = (const float*)d_in[17];
    const float* la_wi = (const float*)d_in[18];
    const float* la_br = (const float*)d_in[19];
    const float* la_bi = (const float*)d_in[20];
    float* out = (float*)d_out;

    dim3 gA((TN/4 + 255)/256, FF, BB);
    kA<<<gA, 256>>>(x, cs_wr, cs_wi, cs_br, cs_bi);

    dim3 gB((TN/4 + 255)/256, FF, BB*C16);
    kB<<<gB, 256>>>(fc_wr, fc_wi, fc_br, fc_bi);

    kC<<<BB*KC_TSPLIT*FF, KC_THREADS>>>(x, tc_wr, tc_wi, tc_br, tc_bi,
                                        ls_wr, ls_wi, ls_br, ls_bi,
                                        la_wr, la_wi, la_br, la_bi, out);
}

// round 14
// speedup vs baseline: 2.4016x; 1.1040x over previous
#include <cuda_runtime.h>
#include <math.h>

#define BB   4
#define C8   8
#define C16  16
#define FF   256
#define TN   2000
#define CHW  (FF*TN)
#define TWO_PI_F     6.283185307179586f
#define INV_TWO_PI_F 0.15915494309189535f

typedef unsigned long long ull;

__device__ float g_s1[BB*2*C16*CHW];
__device__ float g_s2[BB*2*C16*CHW];

__device__ __forceinline__ float mod2pi(float a) {
    return a - floorf(a * INV_TWO_PI_F) * TWO_PI_F;
}

// ---- f32x2 helpers (kA/kB only) ----
__device__ __forceinline__ ull pk(float lo, float hi) {
    ull r; asm("mov.b64 %0,{%1,%2};" : "=l"(r) : "f"(lo), "f"(hi)); return r;
}
__device__ __forceinline__ void upk(ull v, float& lo, float& hi) {
    asm("mov.b64 {%0,%1},%2;" : "=f"(lo), "=f"(hi) : "l"(v));
}
__device__ __forceinline__ ull ffma2(ull a, ull b, ull c) {
    ull d; asm("fma.rn.f32x2 %0,%1,%2,%3;" : "=l"(d) : "l"(a), "l"(b), "l"(c)); return d;
}
__device__ __forceinline__ ull ld64(const float* p) {
    return *reinterpret_cast<const ull*>(p);
}
__device__ __forceinline__ void st64(float* p, ull v) {
    *reinterpret_cast<ull*>(p) = v;
}

// ---------------------------------------------------------------------------
// Kernel A: cLog -> channel_shuffle (8->16) -> cAct.  2 timesteps per thread.
// (R9 version — measured ~105 us, regs 70, occ 36%)
// ---------------------------------------------------------------------------
__global__ void kA(const float* __restrict__ x,
                   const float* __restrict__ wr, const float* __restrict__ wi,
                   const float* __restrict__ br, const float* __restrict__ bi)
{
    const int f = blockIdx.y;
    const int b = blockIdx.z;

    __shared__ ull swr2[C16*C8], swi2[C16*C8];
    __shared__ ull sbr2[C16], sbi2[C16];
    for (int i = threadIdx.x; i < C16*C8; i += blockDim.x) {
        float a = wr[f*C16*C8 + i]; swr2[i] = pk(a, a);
        float c = wi[f*C16*C8 + i]; swi2[i] = pk(c, c);
    }
    if (threadIdx.x < C16) {
        float a = br[f*C16 + threadIdx.x]; sbr2[threadIdx.x] = pk(a, a);
        float c = bi[f*C16 + threadIdx.x]; sbi2[threadIdx.x] = pk(c, c);
    }
    __syncthreads();

    const int tp = 2 * (blockIdx.x * blockDim.x + threadIdx.x);
    if (tp >= TN) return;
    const int off = f*TN + tp;

    ull lm2[C8], ph2[C8];
    #pragma unroll
    for (int c = 0; c < C8; c++) {
        ull xr = ld64(x + ((b*2+0)*C8 + c)*CHW + off);
        ull xi = ld64(x + ((b*2+1)*C8 + c)*CHW + off);
        float r0, r1, i0, i1;
        upk(xr, r0, r1); upk(xi, i0, i1);
        float l0 = 0.5f * __logf(fmaf(r0, r0, fmaf(i0, i0, 1e-12f)));
        float l1 = 0.5f * __logf(fmaf(r1, r1, fmaf(i1, i1, 1e-12f)));
        lm2[c] = pk(l0, l1);
        ph2[c] = pk(atan2f(i0, r0), atan2f(i1, r1));
    }
    #pragma unroll
    for (int o = 0; o < C16; o++) {
        ull sr = sbr2[o], si = sbi2[o];
        #pragma unroll
        for (int c = 0; c < C8; c++) {
            sr = ffma2(swr2[o*C8+c], lm2[c], sr);
            si = ffma2(swi2[o*C8+c], ph2[c], si);
        }
        float s0, s1, p0, p1;
        upk(sr, s0, s1); upk(si, p0, p1);
        float w0 = (__cosf(p0) + 1.0f) * 0.5f;
        float w1 = (__cosf(p1) + 1.0f) * 0.5f;
        st64(g_s1 + ((b*2+0)*C16 + o)*CHW + off, pk(w0*s0, w1*s1));
        st64(g_s1 + ((b*2+1)*C16 + o)*CHW + off, pk(mod2pi(p0), mod2pi(p1)));
    }
}

// ---------------------------------------------------------------------------
// Kernel B: freq_conv (k=5, pad=2) -> cAct.  4 timesteps per thread,
// LDG.128 / STG.128 via ulonglong2, f32x2 math.  (R13 version — ~111 us)
// ---------------------------------------------------------------------------
__global__ void kB(const float* __restrict__ wr, const float* __restrict__ wi,
                   const float* __restrict__ br, const float* __restrict__ bi)
{
    const int f  = blockIdx.y;
    const int bc = blockIdx.z;
    const int b  = bc / C16;
    const int c  = bc % C16;
    const int tp = 4 * (blockIdx.x * blockDim.x + threadIdx.x);
    if (tp >= TN) return;                     // TN % 4 == 0

    const int base_r = ((b*2+0)*C16 + c)*CHW;
    const int base_i = ((b*2+1)*C16 + c)*CHW;

    float b_r = br[c], b_i = bi[c];
    ull yrL = pk(b_r, b_r), yrH = yrL;
    ull yiL = pk(b_i, b_i), yiH = yiL;
    #pragma unroll
    for (int j = 0; j < 5; j++) {
        int ff = f + j - 2;
        if (ff >= 0 && ff < FF) {
            float a = wr[c*5 + j]; float d = wi[c*5 + j];
            ull wa = pk(a, a), wd = pk(d, d);
            ulonglong2 vr = *reinterpret_cast<const ulonglong2*>(g_s1 + base_r + ff*TN + tp);
            ulonglong2 vi = *reinterpret_cast<const ulonglong2*>(g_s1 + base_i + ff*TN + tp);
            yrL = ffma2(wa, vr.x, yrL); yrH = ffma2(wa, vr.y, yrH);
            yiL = ffma2(wd, vi.x, yiL); yiH = ffma2(wd, vi.y, yiH);
        }
    }
    float r0, r1, r2, r3, i0, i1, i2, i3;
    upk(yrL, r0, r1); upk(yrH, r2, r3);
    upk(yiL, i0, i1); upk(yiH, i2, i3);
    float w0 = (__cosf(i0) + 1.0f) * 0.5f;
    float w1 = (__cosf(i1) + 1.0f) * 0.5f;
    float w2 = (__cosf(i2) + 1.0f) * 0.5f;
    float w3 = (__cosf(i3) + 1.0f) * 0.5f;
    ulonglong2 outr, outi;
    outr.x = pk(w0*r0, w1*r1); outr.y = pk(w2*r2, w3*r3);
    outi.x = pk(mod2pi(i0), mod2pi(i1)); outi.y = pk(mod2pi(i2), mod2pi(i3));
    *reinterpret_cast<ulonglong2*>(g_s2 + base_r + f*TN + tp) = outr;
    *reinterpret_cast<ulonglong2*>(g_s2 + base_i + f*TN + tp) = outi;
}

// ---------------------------------------------------------------------------
// Kernel C: R9 champion version, UNCHANGED.  2 t/thread, float2 LDG taps,
// uniform LDS.128 weights, launch_bounds(128,3), t-range split in half.
// (measured ~298 us)
// ---------------------------------------------------------------------------
#define KC_THREADS 128
#define KC_TSPLIT  2
#define KC_TLEN    (TN / KC_TSPLIT)      // 1000

template<bool FULL>
__device__ __forceinline__ void tc_core(
    const float* __restrict__ s2r, const float* __restrict__ s2i,
    const float* __restrict__ stwr, const float* __restrict__ stwi,
    int t0, float ar[8][2], float ai[8][2])
{
    #pragma unroll
    for (int c = 0; c < C16; c++) {
        float vr[10], vi[10];
        if (FULL) {
            #pragma unroll
            for (int m = 0; m < 5; m++) {
                float2 a = *reinterpret_cast<const float2*>(s2r + c*CHW + t0 + 2*m);
                float2 d = *reinterpret_cast<const float2*>(s2i + c*CHW + t0 + 2*m);
                vr[2*m] = a.x; vr[2*m+1] = a.y;
                vi[2*m] = d.x; vi[2*m+1] = d.y;
            }
        } else {
            #pragma unroll
            for (int j = 0; j < 10; j++) {
                int tt = t0 + j;
                vr[j] = (tt < TN) ? s2r[c*CHW + tt] : 0.0f;
                vi[j] = (tt < TN) ? s2i[c*CHW + tt] : 0.0f;
            }
        }
        #pragma unroll
        for (int k = 0; k < 5; k++) {
            const float4 w0 = *reinterpret_cast<const float4*>(stwr + (c*5+k)*8);
            const float4 w1 = *reinterpret_cast<const float4*>(stwr + (c*5+k)*8 + 4);
            const float4 u0 = *reinterpret_cast<const float4*>(stwi + (c*5+k)*8);
            const float4 u1 = *reinterpret_cast<const float4*>(stwi + (c*5+k)*8 + 4);
            const float wrs[8] = {w0.x, w0.y, w0.z, w0.w, w1.x, w1.y, w1.z, w1.w};
            const float wis[8] = {u0.x, u0.y, u0.z, u0.w, u1.x, u1.y, u1.z, u1.w};
            #pragma unroll
            for (int o = 0; o < 8; o++) {
                ar[o][0] = fmaf(wrs[o], vr[2*k],   ar[o][0]);
                ar[o][1] = fmaf(wrs[o], vr[2*k+1], ar[o][1]);
                ai[o][0] = fmaf(wis[o], vi[2*k],   ai[o][0]);
                ai[o][1] = fmaf(wis[o], vi[2*k+1], ai[o][1]);
            }
        }
    }
}

__global__ void __launch_bounds__(KC_THREADS, 3) kC(
    const float* __restrict__ x,
    const float* __restrict__ twr, const float* __restrict__ twi,
    const float* __restrict__ tbr, const float* __restrict__ tbi,
    const float* __restrict__ lwr, const float* __restrict__ lwi,
    const float* __restrict__ lbr, const float* __restrict__ lbi,
    const float* __restrict__ awr, const float* __restrict__ awi,
    const float* __restrict__ abr, const float* __restrict__ abi,
    float* __restrict__ out)
{
    const int f    = blockIdx.x & (FF-1);
    const int bh   = blockIdx.x >> 8;
    const int b    = bh >> 1;               // batch
    const int half = bh & 1;                // t-range half
    const int tBeg = half * KC_TLEN;
    const int tEnd = tBeg + KC_TLEN;

    __shared__ __align__(16) float stwr[C8*C16*5], stwi[C8*C16*5];  // [(c*5+k)*8+o]
    __shared__ float slwr[64], slwi[64], sawr[64], sawi[64];        // [o*8+c]
    __shared__ float stbr[8], stbi[8], slbr[8], slbi[8], sabr[8], sabi[8];

    for (int i = threadIdx.x; i < C8*C16*5; i += KC_THREADS) {
        int o = i & 7, ck = i >> 3;
        int c = ck / 5, k = ck - 5*c;
        stwr[i] = twr[f*C8*C16*5 + (o*C16 + c)*5 + k];
        stwi[i] = twi[f*C8*C16*5 + (o*C16 + c)*5 + k];
    }
    if (threadIdx.x < 64) {
        slwr[threadIdx.x] = lwr[f*64 + threadIdx.x];
        slwi[threadIdx.x] = lwi[f*64 + threadIdx.x];
        sawr[threadIdx.x] = awr[f*64 + threadIdx.x];
        sawi[threadIdx.x] = awi[f*64 + threadIdx.x];
    }
    if (threadIdx.x < 8) {
        stbr[threadIdx.x] = tbr[f*8 + threadIdx.x];
        stbi[threadIdx.x] = tbi[f*8 + threadIdx.x];
        slbr[threadIdx.x] = lbr[f*8 + threadIdx.x];
        slbi[threadIdx.x] = lbi[f*8 + threadIdx.x];
        sabr[threadIdx.x] = abr[f*8 + threadIdx.x];
        sabi[threadIdx.x] = abi[f*8 + threadIdx.x];
    }
    __syncthreads();

    const float* s2r  = g_s2 + (b*2+0)*C16*CHW + f*TN;
    const float* s2i  = g_s2 + (b*2+1)*C16*CHW + f*TN;
    const float* xr_p = x    + (b*2+0)*C8 *CHW + f*TN;
    const float* xi_p = x    + (b*2+1)*C8 *CHW + f*TN;
    float* outr = out + (b*2+0)*C8*CHW + f*TN;
    float* outi = out + (b*2+1)*C8*CHW + f*TN;

    for (int t0 = tBeg + 2*threadIdx.x; t0 < tEnd; t0 += 2*KC_THREADS) {
        float ar[8][2], ai[8][2];
        #pragma unroll
        for (int o = 0; o < 8; o++) {
            ar[o][0] = stbr[o]; ar[o][1] = stbr[o];
            ai[o][0] = stbi[o]; ai[o][1] = stbi[o];
        }

        if (t0 + 9 < TN) tc_core<true >(s2r, s2i, stwr, stwi, t0, ar, ai);
        else             tc_core<false>(s2r, s2i, stwr, stwi, t0, ar, ai);

        float orj[8][2], oij[8][2];
        #pragma unroll
        for (int j = 0; j < 2; j++) {
            // cExp
            float er[8], ei[8];
            #pragma unroll
            for (int o = 0; o < 8; o++) {
                float r = __expf(ar[o][j]);
                float sn, cs;
                __sincosf(ai[o][j], &sn, &cs);
                er[o] = r * cs;
                ei[o] = r * sn;
            }
            // last_shuffle (complex 8x8)
            float sr[8], si[8];
            #pragma unroll
            for (int o = 0; o < 8; o++) {
                float yr = slbr[o] - slbi[o];
                float yi = slbr[o] + slbi[o];
                #pragma unroll
                for (int c = 0; c < 8; c++) {
                    float wr_ = slwr[o*8+c], wi_ = slwi[o*8+c];
                    yr = fmaf(wr_, er[c], yr);
                    yr = fmaf(-wi_, ei[c], yr);
                    yi = fmaf(wr_, ei[c], yi);
                    yi = fmaf(wi_, er[c], yi);
                }
                sr[o] = yr; si[o] = yi;
            }
            // cMul with x (in place)
            #pragma unroll
            for (int c = 0; c < 8; c++) {
                float vxr = xr_p[c*CHW + t0 + j];
                float vxi = xi_p[c*CHW + t0 + j];
                float mr = sr[c]*vxr - si[c]*vxi;
                float mi = sr[c]*vxi + si[c]*vxr;
                sr[c] = mr; si[c] = mi;
            }
            // last (complex 8x8)
            #pragma unroll
            for (int o = 0; o < 8; o++) {
                float yr = sabr[o] - sabi[o];
                float yi = sabr[o] + sabi[o];
                #pragma unroll
                for (int c = 0; c < 8; c++) {
                    float wr_ = sawr[o*8+c], wi_ = sawi[o*8+c];
                    yr = fmaf(wr_, sr[c], yr);
                    yr = fmaf(-wi_, si[c], yr);
                    yi = fmaf(wr_, si[c], yi);
                    yi = fmaf(wi_, sr[c], yi);
                }
                orj[o][j] = yr; oij[o][j] = yi;
            }
        }
        #pragma unroll
        for (int o = 0; o < 8; o++) {
            *reinterpret_cast<float2*>(outr + o*CHW + t0) = make_float2(orj[o][0], orj[o][1]);
            *reinterpret_cast<float2*>(outi + o*CHW + t0) = make_float2(oij[o][0], oij[o][1]);
        }
    }
}

// ---------------------------------------------------------------------------
extern "C" void kernel_launch(void* const* d_in, const int* in_sizes, int n_in,
                              void* d_out, int out_size)
{
    const float* x     = (const float*)d_in[0];
    const float* cs_wr = (const float*)d_in[1];
    const float* cs_wi = (const float*)d_in[2];
    const float* cs_br = (const float*)d_in[3];
    const float* cs_bi = (const float*)d_in[4];
    const float* fc_wr = (const float*)d_in[5];
    const float* fc_wi = (const float*)d_in[6];
    const float* fc_br = (const float*)d_in[7];
    const float* fc_bi = (const float*)d_in[8];
    const float* tc_wr = (const float*)d_in[9];
    const float* tc_wi = (const float*)d_in[10];
    const float* tc_br = (const float*)d_in[11];
    const float* tc_bi = (const float*)d_in[12];
    const float* ls_wr = (const float*)d_in[13];
    const float* ls_wi = (const float*)d_in[14];
    const float* ls_br = (const float*)d_in[15];
    const float* ls_bi = (const float*)d_in[16];
    const float* la_wr = (const float*)d_in[17];
    const float* la_wi = (const float*)d_in[18];
    const float* la_br = (const float*)d_in[19];
    const float* la_bi = (const float*)d_in[20];
    float* out = (float*)d_out;

    dim3 gA((TN/2 + 255)/256, FF, BB);
    kA<<<gA, 256>>>(x, cs_wr, cs_wi, cs_br, cs_bi);

    dim3 gB((TN/4 + 255)/256, FF, BB*C16);
    kB<<<gB, 256>>>(fc_wr, fc_wi, fc_br, fc_bi);

    kC<<<BB*KC_TSPLIT*FF, KC_THREADS>>>(x, tc_wr, tc_wi, tc_br, tc_bi,
                                        ls_wr, ls_wi, ls_br, ls_bi,
                                        la_wr, la_wi, la_br, la_bi, out);
}

// round 15
// speedup vs baseline: 2.4613x; 1.0249x over previous
#include <cuda_runtime.h>
#include <math.h>

#define BB   4
#define C8   8
#define C16  16
#define FF   256
#define TN   2000
#define CHW  (FF*TN)
#define TWO_PI_F     6.283185307179586f
#define INV_TWO_PI_F 0.15915494309189535f

typedef unsigned long long ull;

__device__ float g_s1[BB*2*C16*CHW];
__device__ float g_s2[BB*2*C16*CHW];

__device__ __forceinline__ float mod2pi(float a) {
    return a - floorf(a * INV_TWO_PI_F) * TWO_PI_F;
}

// ---- f32x2 helpers (kA/kB only) ----
__device__ __forceinline__ ull pk(float lo, float hi) {
    ull r; asm("mov.b64 %0,{%1,%2};" : "=l"(r) : "f"(lo), "f"(hi)); return r;
}
__device__ __forceinline__ void upk(ull v, float& lo, float& hi) {
    asm("mov.b64 {%0,%1},%2;" : "=f"(lo), "=f"(hi) : "l"(v));
}
__device__ __forceinline__ ull ffma2(ull a, ull b, ull c) {
    ull d; asm("fma.rn.f32x2 %0,%1,%2,%3;" : "=l"(d) : "l"(a), "l"(b), "l"(c)); return d;
}
__device__ __forceinline__ ull ld64(const float* p) {
    return *reinterpret_cast<const ull*>(p);
}
__device__ __forceinline__ void st64(float* p, ull v) {
    *reinterpret_cast<ull*>(p) = v;
}

// ---------------------------------------------------------------------------
// Kernel A: cLog -> channel_shuffle (8->16) -> cAct.  2 timesteps per thread.
// launch_bounds(256,4): 64-reg cap -> 4 blocks/SM (50% occ).
// ---------------------------------------------------------------------------
__global__ void __launch_bounds__(256, 4) kA(
    const float* __restrict__ x,
    const float* __restrict__ wr, const float* __restrict__ wi,
    const float* __restrict__ br, const float* __restrict__ bi)
{
    const int f = blockIdx.y;
    const int b = blockIdx.z;

    __shared__ ull swr2[C16*C8], swi2[C16*C8];
    __shared__ ull sbr2[C16], sbi2[C16];
    for (int i = threadIdx.x; i < C16*C8; i += blockDim.x) {
        float a = wr[f*C16*C8 + i]; swr2[i] = pk(a, a);
        float c = wi[f*C16*C8 + i]; swi2[i] = pk(c, c);
    }
    if (threadIdx.x < C16) {
        float a = br[f*C16 + threadIdx.x]; sbr2[threadIdx.x] = pk(a, a);
        float c = bi[f*C16 + threadIdx.x]; sbi2[threadIdx.x] = pk(c, c);
    }
    __syncthreads();

    const int tp = 2 * (blockIdx.x * blockDim.x + threadIdx.x);
    if (tp >= TN) return;
    const int off = f*TN + tp;

    ull lm2[C8], ph2[C8];
    #pragma unroll
    for (int c = 0; c < C8; c++) {
        ull xr = ld64(x + ((b*2+0)*C8 + c)*CHW + off);
        ull xi = ld64(x + ((b*2+1)*C8 + c)*CHW + off);
        float r0, r1, i0, i1;
        upk(xr, r0, r1); upk(xi, i0, i1);
        float l0 = 0.5f * __logf(fmaf(r0, r0, fmaf(i0, i0, 1e-12f)));
        float l1 = 0.5f * __logf(fmaf(r1, r1, fmaf(i1, i1, 1e-12f)));
        lm2[c] = pk(l0, l1);
        ph2[c] = pk(atan2f(i0, r0), atan2f(i1, r1));
    }
    #pragma unroll
    for (int o = 0; o < C16; o++) {
        ull sr = sbr2[o], si = sbi2[o];
        #pragma unroll
        for (int c = 0; c < C8; c++) {
            sr = ffma2(swr2[o*C8+c], lm2[c], sr);
            si = ffma2(swi2[o*C8+c], ph2[c], si);
        }
        float s0, s1, p0, p1;
        upk(sr, s0, s1); upk(si, p0, p1);
        float w0 = (__cosf(p0) + 1.0f) * 0.5f;
        float w1 = (__cosf(p1) + 1.0f) * 0.5f;
        st64(g_s1 + ((b*2+0)*C16 + o)*CHW + off, pk(w0*s0, w1*s1));
        st64(g_s1 + ((b*2+1)*C16 + o)*CHW + off, pk(mod2pi(p0), mod2pi(p1)));
    }
}

// ---------------------------------------------------------------------------
// Kernel B: freq_conv (k=5, pad=2) -> cAct.  4 timesteps per thread,
// LDG.128 / STG.128 via ulonglong2, f32x2 math.  (R13 version — ~111 us)
// ---------------------------------------------------------------------------
__global__ void kB(const float* __restrict__ wr, const float* __restrict__ wi,
                   const float* __restrict__ br, const float* __restrict__ bi)
{
    const int f  = blockIdx.y;
    const int bc = blockIdx.z;
    const int b  = bc / C16;
    const int c  = bc % C16;
    const int tp = 4 * (blockIdx.x * blockDim.x + threadIdx.x);
    if (tp >= TN) return;                     // TN % 4 == 0

    const int base_r = ((b*2+0)*C16 + c)*CHW;
    const int base_i = ((b*2+1)*C16 + c)*CHW;

    float b_r = br[c], b_i = bi[c];
    ull yrL = pk(b_r, b_r), yrH = yrL;
    ull yiL = pk(b_i, b_i), yiH = yiL;
    #pragma unroll
    for (int j = 0; j < 5; j++) {
        int ff = f + j - 2;
        if (ff >= 0 && ff < FF) {
            float a = wr[c*5 + j]; float d = wi[c*5 + j];
            ull wa = pk(a, a), wd = pk(d, d);
            ulonglong2 vr = *reinterpret_cast<const ulonglong2*>(g_s1 + base_r + ff*TN + tp);
            ulonglong2 vi = *reinterpret_cast<const ulonglong2*>(g_s1 + base_i + ff*TN + tp);
            yrL = ffma2(wa, vr.x, yrL); yrH = ffma2(wa, vr.y, yrH);
            yiL = ffma2(wd, vi.x, yiL); yiH = ffma2(wd, vi.y, yiH);
        }
    }
    float r0, r1, r2, r3, i0, i1, i2, i3;
    upk(yrL, r0, r1); upk(yrH, r2, r3);
    upk(yiL, i0, i1); upk(yiH, i2, i3);
    float w0 = (__cosf(i0) + 1.0f) * 0.5f;
    float w1 = (__cosf(i1) + 1.0f) * 0.5f;
    float w2 = (__cosf(i2) + 1.0f) * 0.5f;
    float w3 = (__cosf(i3) + 1.0f) * 0.5f;
    ulonglong2 outr, outi;
    outr.x = pk(w0*r0, w1*r1); outr.y = pk(w2*r2, w3*r3);
    outi.x = pk(mod2pi(i0), mod2pi(i1)); outi.y = pk(mod2pi(i2), mod2pi(i3));
    *reinterpret_cast<ulonglong2*>(g_s2 + base_r + f*TN + tp) = outr;
    *reinterpret_cast<ulonglong2*>(g_s2 + base_i + f*TN + tp) = outi;
}

// ---------------------------------------------------------------------------
// Kernel C: R9 champion structure.  2 t/thread, float2 LDG taps, uniform
// LDS.128 weights, launch_bounds(128,3).  t-range split in QUARTERS for
// finer wave granularity (4096 blocks, ~9.2 waves).
// ---------------------------------------------------------------------------
#define KC_THREADS 128
#define KC_TSPLIT  4
#define KC_TLEN    (TN / KC_TSPLIT)      // 500

template<bool FULL>
__device__ __forceinline__ void tc_core(
    const float* __restrict__ s2r, const float* __restrict__ s2i,
    const float* __restrict__ stwr, const float* __restrict__ stwi,
    int t0, float ar[8][2], float ai[8][2])
{
    #pragma unroll
    for (int c = 0; c < C16; c++) {
        float vr[10], vi[10];
        if (FULL) {
            #pragma unroll
            for (int m = 0; m < 5; m++) {
                float2 a = *reinterpret_cast<const float2*>(s2r + c*CHW + t0 + 2*m);
                float2 d = *reinterpret_cast<const float2*>(s2i + c*CHW + t0 + 2*m);
                vr[2*m] = a.x; vr[2*m+1] = a.y;
                vi[2*m] = d.x; vi[2*m+1] = d.y;
            }
        } else {
            #pragma unroll
            for (int j = 0; j < 10; j++) {
                int tt = t0 + j;
                vr[j] = (tt < TN) ? s2r[c*CHW + tt] : 0.0f;
                vi[j] = (tt < TN) ? s2i[c*CHW + tt] : 0.0f;
            }
        }
        #pragma unroll
        for (int k = 0; k < 5; k++) {
            const float4 w0 = *reinterpret_cast<const float4*>(stwr + (c*5+k)*8);
            const float4 w1 = *reinterpret_cast<const float4*>(stwr + (c*5+k)*8 + 4);
            const float4 u0 = *reinterpret_cast<const float4*>(stwi + (c*5+k)*8);
            const float4 u1 = *reinterpret_cast<const float4*>(stwi + (c*5+k)*8 + 4);
            const float wrs[8] = {w0.x, w0.y, w0.z, w0.w, w1.x, w1.y, w1.z, w1.w};
            const float wis[8] = {u0.x, u0.y, u0.z, u0.w, u1.x, u1.y, u1.z, u1.w};
            #pragma unroll
            for (int o = 0; o < 8; o++) {
                ar[o][0] = fmaf(wrs[o], vr[2*k],   ar[o][0]);
                ar[o][1] = fmaf(wrs[o], vr[2*k+1], ar[o][1]);
                ai[o][0] = fmaf(wis[o], vi[2*k],   ai[o][0]);
                ai[o][1] = fmaf(wis[o], vi[2*k+1], ai[o][1]);
            }
        }
    }
}

__global__ void __launch_bounds__(KC_THREADS, 3) kC(
    const float* __restrict__ x,
    const float* __restrict__ twr, const float* __restrict__ twi,
    const float* __restrict__ tbr, const float* __restrict__ tbi,
    const float* __restrict__ lwr, const float* __restrict__ lwi,
    const float* __restrict__ lbr, const float* __restrict__ lbi,
    const float* __restrict__ awr, const float* __restrict__ awi,
    const float* __restrict__ abr, const float* __restrict__ abi,
    float* __restrict__ out)
{
    const int f    = blockIdx.x & (FF-1);
    const int bh   = blockIdx.x >> 8;
    const int b    = bh >> 2;               // batch
    const int q    = bh & 3;                // t-range quarter
    const int tBeg = q * KC_TLEN;
    const int tEnd = tBeg + KC_TLEN;

    __shared__ __align__(16) float stwr[C8*C16*5], stwi[C8*C16*5];  // [(c*5+k)*8+o]
    __shared__ float slwr[64], slwi[64], sawr[64], sawi[64];        // [o*8+c]
    __shared__ float stbr[8], stbi[8], slbr[8], slbi[8], sabr[8], sabi[8];

    for (int i = threadIdx.x; i < C8*C16*5; i += KC_THREADS) {
        int o = i & 7, ck = i >> 3;
        int c = ck / 5, k = ck - 5*c;
        stwr[i] = twr[f*C8*C16*5 + (o*C16 + c)*5 + k];
        stwi[i] = twi[f*C8*C16*5 + (o*C16 + c)*5 + k];
    }
    if (threadIdx.x < 64) {
        slwr[threadIdx.x] = lwr[f*64 + threadIdx.x];
        slwi[threadIdx.x] = lwi[f*64 + threadIdx.x];
        sawr[threadIdx.x] = awr[f*64 + threadIdx.x];
        sawi[threadIdx.x] = awi[f*64 + threadIdx.x];
    }
    if (threadIdx.x < 8) {
        stbr[threadIdx.x] = tbr[f*8 + threadIdx.x];
        stbi[threadIdx.x] = tbi[f*8 + threadIdx.x];
        slbr[threadIdx.x] = lbr[f*8 + threadIdx.x];
        slbi[threadIdx.x] = lbi[f*8 + threadIdx.x];
        sabr[threadIdx.x] = abr[f*8 + threadIdx.x];
        sabi[threadIdx.x] = abi[f*8 + threadIdx.x];
    }
    __syncthreads();

    const float* s2r  = g_s2 + (b*2+0)*C16*CHW + f*TN;
    const float* s2i  = g_s2 + (b*2+1)*C16*CHW + f*TN;
    const float* xr_p = x    + (b*2+0)*C8 *CHW + f*TN;
    const float* xi_p = x    + (b*2+1)*C8 *CHW + f*TN;
    float* outr = out + (b*2+0)*C8*CHW + f*TN;
    float* outi = out + (b*2+1)*C8*CHW + f*TN;

    for (int t0 = tBeg + 2*threadIdx.x; t0 < tEnd; t0 += 2*KC_THREADS) {
        float ar[8][2], ai[8][2];
        #pragma unroll
        for (int o = 0; o < 8; o++) {
            ar[o][0] = stbr[o]; ar[o][1] = stbr[o];
            ai[o][0] = stbi[o]; ai[o][1] = stbi[o];
        }

        if (t0 + 9 < TN) tc_core<true >(s2r, s2i, stwr, stwi, t0, ar, ai);
        else             tc_core<false>(s2r, s2i, stwr, stwi, t0, ar, ai);

        float orj[8][2], oij[8][2];
        #pragma unroll
        for (int j = 0; j < 2; j++) {
            // cExp
            float er[8], ei[8];
            #pragma unroll
            for (int o = 0; o < 8; o++) {
                float r = __expf(ar[o][j]);
                float sn, cs;
                __sincosf(ai[o][j], &sn, &cs);
                er[o] = r * cs;
                ei[o] = r * sn;
            }
            // last_shuffle (complex 8x8)
            float sr[8], si[8];
            #pragma unroll
            for (int o = 0; o < 8; o++) {
                float yr = slbr[o] - slbi[o];
                float yi = slbr[o] + slbi[o];
                #pragma unroll
                for (int c = 0; c < 8; c++) {
                    float wr_ = slwr[o*8+c], wi_ = slwi[o*8+c];
                    yr = fmaf(wr_, er[c], yr);
                    yr = fmaf(-wi_, ei[c], yr);
                    yi = fmaf(wr_, ei[c], yi);
                    yi = fmaf(wi_, er[c], yi);
                }
                sr[o] = yr; si[o] = yi;
            }
            // cMul with x (in place)
            #pragma unroll
            for (int c = 0; c < 8; c++) {
                float vxr = xr_p[c*CHW + t0 + j];
                float vxi = xi_p[c*CHW + t0 + j];
                float mr = sr[c]*vxr - si[c]*vxi;
                float mi = sr[c]*vxi + si[c]*vxr;
                sr[c] = mr; si[c] = mi;
            }
            // last (complex 8x8)
            #pragma unroll
            for (int o = 0; o < 8; o++) {
                float yr = sabr[o] - sabi[o];
                float yi = sabr[o] + sabi[o];
                #pragma unroll
                for (int c = 0; c < 8; c++) {
                    float wr_ = sawr[o*8+c], wi_ = sawi[o*8+c];
                    yr = fmaf(wr_, sr[c], yr);
                    yr = fmaf(-wi_, si[c], yr);
                    yi = fmaf(wr_, si[c], yi);
                    yi = fmaf(wi_, sr[c], yi);
                }
                orj[o][j] = yr; oij[o][j] = yi;
            }
        }
        #pragma unroll
        for (int o = 0; o < 8; o++) {
            *reinterpret_cast<float2*>(outr + o*CHW + t0) = make_float2(orj[o][0], orj[o][1]);
            *reinterpret_cast<float2*>(outi + o*CHW + t0) = make_float2(oij[o][0], oij[o][1]);
        }
    }
}

// ---------------------------------------------------------------------------
extern "C" void kernel_launch(void* const* d_in, const int* in_sizes, int n_in,
                              void* d_out, int out_size)
{
    const float* x     = (const float*)d_in[0];
    const float* cs_wr = (const float*)d_in[1];
    const float* cs_wi = (const float*)d_in[2];
    const float* cs_br = (const float*)d_in[3];
    const float* cs_bi = (const float*)d_in[4];
    const float* fc_wr = (const float*)d_in[5];
    const float* fc_wi = (const float*)d_in[6];
    const float* fc_br = (const float*)d_in[7];
    const float* fc_bi = (const float*)d_in[8];
    const float* tc_wr = (const float*)d_in[9];
    const float* tc_wi = (const float*)d_in[10];
    const float* tc_br = (const float*)d_in[11];
    const float* tc_bi = (const float*)d_in[12];
    const float* ls_wr = (const float*)d_in[13];
    const float* ls_wi = (const float*)d_in[14];
    const float* ls_br = (const float*)d_in[15];
    const float* ls_bi = (const float*)d_in[16];
    const float* la_wr = (const float*)d_in[17];
    const float* la_wi = (const float*)d_in[18];
    const float* la_br = (const float*)d_in[19];
    const float* la_bi = (const float*)d_in[20];
    float* out = (float*)d_out;

    dim3 gA((TN/2 + 255)/256, FF, BB);
    kA<<<gA, 256>>>(x, cs_wr, cs_wi, cs_br, cs_bi);

    dim3 gB((TN/4 + 255)/256, FF, BB*C16);
    kB<<<gB, 256>>>(fc_wr, fc_wi, fc_br, fc_bi);

    kC<<<BB*KC_TSPLIT*FF, KC_THREADS>>>(x, tc_wr, tc_wi, tc_br, tc_bi,
                                        ls_wr, ls_wi, ls_br, ls_bi,
                                        la_wr, la_wi, la_br, la_bi, out);
}

// round 17
// speedup vs baseline: 2.5249x; 1.0258x over previous
#include <cuda_runtime.h>
#include <math.h>

#define BB   4
#define C8   8
#define C16  16
#define FF   256
#define TN   2000
#define CHW  (FF*TN)
#define TWO_PI_F     6.283185307179586f
#define INV_TWO_PI_F 0.15915494309189535f

typedef unsigned long long ull;

__device__ float g_s1[BB*2*C16*CHW];
__device__ float g_s2[BB*2*C16*CHW];

__device__ __forceinline__ float mod2pi(float a) {
    return a - floorf(a * INV_TWO_PI_F) * TWO_PI_F;
}

// Fast atan2, Cephes-style: range-reduce to [0, tan(pi/8)], degree-9 odd
// minimax. Max error ~1e-7 rad (libm-class), ~20 instr vs libm's ~40.
// Inputs are continuous Gaussians -> (0,0) never occurs.
__device__ __forceinline__ float fast_atan2f(float y, float x) {
    float ax = fabsf(x), ay = fabsf(y);
    float mx = fmaxf(ax, ay), mn = fminf(ax, ay);
    float a  = __fdividef(mn, mx);            // [0,1]
    bool big = a > 0.4142135623730951f;       // tan(pi/8)
    float z  = big ? __fdividef(a - 1.0f, a + 1.0f) : a;   // [-0.4142, 0.4142]
    float s  = z * z;
    float p  = fmaf(s, fmaf(s, fmaf(s, 8.05374449538e-2f,
                                      -1.38776856032e-1f),
                               1.99777106478e-1f),
                      -3.33329491539e-1f);
    float r  = fmaf(z * s, p, z);
    if (big)       r += 0.7853981633974483f;  // + pi/4
    if (ay > ax)   r = 1.5707963267948966f - r;
    if (x < 0.0f)  r = 3.1415926535897931f - r;
    return (y < 0.0f) ? -r : r;
}

// ---- f32x2 helpers (kA/kB only) ----
__device__ __forceinline__ ull pk(float lo, float hi) {
    ull r; asm("mov.b64 %0,{%1,%2};" : "=l"(r) : "f"(lo), "f"(hi)); return r;
}
__device__ __forceinline__ void upk(ull v, float& lo, float& hi) {
    asm("mov.b64 {%0,%1},%2;" : "=f"(lo), "=f"(hi) : "l"(v));
}
__device__ __forceinline__ ull ffma2(ull a, ull b, ull c) {
    ull d; asm("fma.rn.f32x2 %0,%1,%2,%3;" : "=l"(d) : "l"(a), "l"(b), "l"(c)); return d;
}
__device__ __forceinline__ ull ld64(const float* p) {
    return *reinterpret_cast<const ull*>(p);
}
__device__ __forceinline__ void st64(float* p, ull v) {
    *reinterpret_cast<ull*>(p) = v;
}

// ---------------------------------------------------------------------------
// Kernel A: cLog -> channel_shuffle (8->16) -> cAct.  2 timesteps per thread.
// launch_bounds(256,4): 64-reg cap, 46% occ.  fast_atan2f (1e-7 class).
// ---------------------------------------------------------------------------
__global__ void __launch_bounds__(256, 4) kA(
    const float* __restrict__ x,
    const float* __restrict__ wr, const float* __restrict__ wi,
    const float* __restrict__ br, const float* __restrict__ bi)
{
    const int f = blockIdx.y;
    const int b = blockIdx.z;

    __shared__ ull swr2[C16*C8], swi2[C16*C8];
    __shared__ ull sbr2[C16], sbi2[C16];
    for (int i = threadIdx.x; i < C16*C8; i += blockDim.x) {
        float a = wr[f*C16*C8 + i]; swr2[i] = pk(a, a);
        float c = wi[f*C16*C8 + i]; swi2[i] = pk(c, c);
    }
    if (threadIdx.x < C16) {
        float a = br[f*C16 + threadIdx.x]; sbr2[threadIdx.x] = pk(a, a);
        float c = bi[f*C16 + threadIdx.x]; sbi2[threadIdx.x] = pk(c, c);
    }
    __syncthreads();

    const int tp = 2 * (blockIdx.x * blockDim.x + threadIdx.x);
    if (tp >= TN) return;
    const int off = f*TN + tp;

    ull lm2[C8], ph2[C8];
    #pragma unroll
    for (int c = 0; c < C8; c++) {
        ull xr = ld64(x + ((b*2+0)*C8 + c)*CHW + off);
        ull xi = ld64(x + ((b*2+1)*C8 + c)*CHW + off);
        float r0, r1, i0, i1;
        upk(xr, r0, r1); upk(xi, i0, i1);
        float l0 = 0.5f * __logf(fmaf(r0, r0, fmaf(i0, i0, 1e-12f)));
        float l1 = 0.5f * __logf(fmaf(r1, r1, fmaf(i1, i1, 1e-12f)));
        lm2[c] = pk(l0, l1);
        ph2[c] = pk(fast_atan2f(i0, r0), fast_atan2f(i1, r1));
    }
    #pragma unroll
    for (int o = 0; o < C16; o++) {
        ull sr = sbr2[o], si = sbi2[o];
        #pragma unroll
        for (int c = 0; c < C8; c++) {
            sr = ffma2(swr2[o*C8+c], lm2[c], sr);
            si = ffma2(swi2[o*C8+c], ph2[c], si);
        }
        float s0, s1, p0, p1;
        upk(sr, s0, s1); upk(si, p0, p1);
        float w0 = (__cosf(p0) + 1.0f) * 0.5f;
        float w1 = (__cosf(p1) + 1.0f) * 0.5f;
        st64(g_s1 + ((b*2+0)*C16 + o)*CHW + off, pk(w0*s0, w1*s1));
        st64(g_s1 + ((b*2+1)*C16 + o)*CHW + off, pk(mod2pi(p0), mod2pi(p1)));
    }
}

// ---------------------------------------------------------------------------
// Kernel B: freq_conv (k=5, pad=2) -> cAct.  4 timesteps per thread,
// LDG.128 / STG.128 via ulonglong2, f32x2 math.  (R13 version — ~111 us)
// ---------------------------------------------------------------------------
__global__ void kB(const float* __restrict__ wr, const float* __restrict__ wi,
                   const float* __restrict__ br, const float* __restrict__ bi)
{
    const int f  = blockIdx.y;
    const int bc = blockIdx.z;
    const int b  = bc / C16;
    const int c  = bc % C16;
    const int tp = 4 * (blockIdx.x * blockDim.x + threadIdx.x);
    if (tp >= TN) return;                     // TN % 4 == 0

    const int base_r = ((b*2+0)*C16 + c)*CHW;
    const int base_i = ((b*2+1)*C16 + c)*CHW;

    float b_r = br[c], b_i = bi[c];
    ull yrL = pk(b_r, b_r), yrH = yrL;
    ull yiL = pk(b_i, b_i), yiH = yiL;
    #pragma unroll
    for (int j = 0; j < 5; j++) {
        int ff = f + j - 2;
        if (ff >= 0 && ff < FF) {
            float a = wr[c*5 + j]; float d = wi[c*5 + j];
            ull wa = pk(a, a), wd = pk(d, d);
            ulonglong2 vr = *reinterpret_cast<const ulonglong2*>(g_s1 + base_r + ff*TN + tp);
            ulonglong2 vi = *reinterpret_cast<const ulonglong2*>(g_s1 + base_i + ff*TN + tp);
            yrL = ffma2(wa, vr.x, yrL); yrH = ffma2(wa, vr.y, yrH);
            yiL = ffma2(wd, vi.x, yiL); yiH = ffma2(wd, vi.y, yiH);
        }
    }
    float r0, r1, r2, r3, i0, i1, i2, i3;
    upk(yrL, r0, r1); upk(yrH, r2, r3);
    upk(yiL, i0, i1); upk(yiH, i2, i3);
    float w0 = (__cosf(i0) + 1.0f) * 0.5f;
    float w1 = (__cosf(i1) + 1.0f) * 0.5f;
    float w2 = (__cosf(i2) + 1.0f) * 0.5f;
    float w3 = (__cosf(i3) + 1.0f) * 0.5f;
    ulonglong2 outr, outi;
    outr.x = pk(w0*r0, w1*r1); outr.y = pk(w2*r2, w3*r3);
    outi.x = pk(mod2pi(i0), mod2pi(i1)); outi.y = pk(mod2pi(i2), mod2pi(i3));
    *reinterpret_cast<ulonglong2*>(g_s2 + base_r + f*TN + tp) = outr;
    *reinterpret_cast<ulonglong2*>(g_s2 + base_i + f*TN + tp) = outi;
}

// ---------------------------------------------------------------------------
// Kernel C: R9 champion structure.  2 t/thread, float2 LDG taps, uniform
// LDS.128 weights, launch_bounds(128,3), t-range split in quarters.
// (measured ~287 us — unchanged)
// ---------------------------------------------------------------------------
#define KC_THREADS 128
#define KC_TSPLIT  4
#define KC_TLEN    (TN / KC_TSPLIT)      // 500

template<bool FULL>
__device__ __forceinline__ void tc_core(
    const float* __restrict__ s2r, const float* __restrict__ s2i,
    const float* __restrict__ stwr, const float* __restrict__ stwi,
    int t0, float ar[8][2], float ai[8][2])
{
    #pragma unroll
    for (int c = 0; c < C16; c++) {
        float vr[10], vi[10];
        if (FULL) {
            #pragma unroll
            for (int m = 0; m < 5; m++) {
                float2 a = *reinterpret_cast<const float2*>(s2r + c*CHW + t0 + 2*m);
                float2 d = *reinterpret_cast<const float2*>(s2i + c*CHW + t0 + 2*m);
                vr[2*m] = a.x; vr[2*m+1] = a.y;
                vi[2*m] = d.x; vi[2*m+1] = d.y;
            }
        } else {
            #pragma unroll
            for (int j = 0; j < 10; j++) {
                int tt = t0 + j;
                vr[j] = (tt < TN) ? s2r[c*CHW + tt] : 0.0f;
                vi[j] = (tt < TN) ? s2i[c*CHW + tt] : 0.0f;
            }
        }
        #pragma unroll
        for (int k = 0; k < 5; k++) {
            const float4 w0 = *reinterpret_cast<const float4*>(stwr + (c*5+k)*8);
            const float4 w1 = *reinterpret_cast<const float4*>(stwr + (c*5+k)*8 + 4);
            const float4 u0 = *reinterpret_cast<const float4*>(stwi + (c*5+k)*8);
            const float4 u1 = *reinterpret_cast<const float4*>(stwi + (c*5+k)*8 + 4);
            const float wrs[8] = {w0.x, w0.y, w0.z, w0.w, w1.x, w1.y, w1.z, w1.w};
            const float wis[8] = {u0.x, u0.y, u0.z, u0.w, u1.x, u1.y, u1.z, u1.w};
            #pragma unroll
            for (int o = 0; o < 8; o++) {
                ar[o][0] = fmaf(wrs[o], vr[2*k],   ar[o][0]);
                ar[o][1] = fmaf(wrs[o], vr[2*k+1], ar[o][1]);
                ai[o][0] = fmaf(wis[o], vi[2*k],   ai[o][0]);
                ai[o][1] = fmaf(wis[o], vi[2*k+1], ai[o][1]);
            }
        }
    }
}

__global__ void __launch_bounds__(KC_THREADS, 3) kC(
    const float* __restrict__ x,
    const float* __restrict__ twr, const float* __restrict__ twi,
    const float* __restrict__ tbr, const float* __restrict__ tbi,
    const float* __restrict__ lwr, const float* __restrict__ lwi,
    const float* __restrict__ lbr, const float* __restrict__ lbi,
    const float* __restrict__ awr, const float* __restrict__ awi,
    const float* __restrict__ abr, const float* __restrict__ abi,
    float* __restrict__ out)
{
    const int f    = blockIdx.x & (FF-1);
    const int bh   = blockIdx.x >> 8;
    const int b    = bh >> 2;               // batch
    const int q    = bh & 3;                // t-range quarter
    const int tBeg = q * KC_TLEN;
    const int tEnd = tBeg + KC_TLEN;

    __shared__ __align__(16) float stwr[C8*C16*5], stwi[C8*C16*5];  // [(c*5+k)*8+o]
    __shared__ float slwr[64], slwi[64], sawr[64], sawi[64];        // [o*8+c]
    __shared__ float stbr[8], stbi[8], slbr[8], slbi[8], sabr[8], sabi[8];

    for (int i = threadIdx.x; i < C8*C16*5; i += KC_THREADS) {
        int o = i & 7, ck = i >> 3;
        int c = ck / 5, k = ck - 5*c;
        stwr[i] = twr[f*C8*C16*5 + (o*C16 + c)*5 + k];
        stwi[i] = twi[f*C8*C16*5 + (o*C16 + c)*5 + k];
    }
    if (threadIdx.x < 64) {
        slwr[threadIdx.x] = lwr[f*64 + threadIdx.x];
        slwi[threadIdx.x] = lwi[f*64 + threadIdx.x];
        sawr[threadIdx.x] = awr[f*64 + threadIdx.x];
        sawi[threadIdx.x] = awi[f*64 + threadIdx.x];
    }
    if (threadIdx.x < 8) {
        stbr[threadIdx.x] = tbr[f*8 + threadIdx.x];
        stbi[threadIdx.x] = tbi[f*8 + threadIdx.x];
        slbr[threadIdx.x] = lbr[f*8 + threadIdx.x];
        slbi[threadIdx.x] = lbi[f*8 + threadIdx.x];
        sabr[threadIdx.x] = abr[f*8 + threadIdx.x];
        sabi[threadIdx.x] = abi[f*8 + threadIdx.x];
    }
    __syncthreads();

    const float* s2r  = g_s2 + (b*2+0)*C16*CHW + f*TN;
    const float* s2i  = g_s2 + (b*2+1)*C16*CHW + f*TN;
    const float* xr_p = x    + (b*2+0)*C8 *CHW + f*TN;
    const float* xi_p = x    + (b*2+1)*C8 *CHW + f*TN;
    float* outr = out + (b*2+0)*C8*CHW + f*TN;
    float* outi = out + (b*2+1)*C8*CHW + f*TN;

    for (int t0 = tBeg + 2*threadIdx.x; t0 < tEnd; t0 += 2*KC_THREADS) {
        float ar[8][2], ai[8][2];
        #pragma unroll
        for (int o = 0; o < 8; o++) {
            ar[o][0] = stbr[o]; ar[o][1] = stbr[o];
            ai[o][0] = stbi[o]; ai[o][1] = stbi[o];
        }

        if (t0 + 9 < TN) tc_core<true >(s2r, s2i, stwr, stwi, t0, ar, ai);
        else             tc_core<false>(s2r, s2i, stwr, stwi, t0, ar, ai);

        float orj[8][2], oij[8][2];
        #pragma unroll
        for (int j = 0; j < 2; j++) {
            // cExp
            float er[8], ei[8];
            #pragma unroll
            for (int o = 0; o < 8; o++) {
                float r = __expf(ar[o][j]);
                float sn, cs;
                __sincosf(ai[o][j], &sn, &cs);
                er[o] = r * cs;
                ei[o] = r * sn;
            }
            // last_shuffle (complex 8x8)
            float sr[8], si[8];
            #pragma unroll
            for (int o = 0; o < 8; o++) {
                float yr = slbr[o] - slbi[o];
                float yi = slbr[o] + slbi[o];
                #pragma unroll
                for (int c = 0; c < 8; c++) {
                    float wr_ = slwr[o*8+c], wi_ = slwi[o*8+c];
                    yr = fmaf(wr_, er[c], yr);
                    yr = fmaf(-wi_, ei[c], yr);
                    yi = fmaf(wr_, ei[c], yi);
                    yi = fmaf(wi_, er[c], yi);
                }
                sr[o] = yr; si[o] = yi;
            }
            // cMul with x (in place)
            #pragma unroll
            for (int c = 0; c < 8; c++) {
                float vxr = xr_p[c*CHW + t0 + j];
                float vxi = xi_p[c*CHW + t0 + j];
                float mr = sr[c]*vxr - si[c]*vxi;
                float mi = sr[c]*vxi + si[c]*vxr;
                sr[c] = mr; si[c] = mi;
            }
            // last (complex 8x8)
            #pragma unroll
            for (int o = 0; o < 8; o++) {
                float yr = sabr[o] - sabi[o];
                float yi = sabr[o] + sabi[o];
                #pragma unroll
                for (int c = 0; c < 8; c++) {
                    float wr_ = sawr[o*8+c], wi_ = sawi[o*8+c];
                    yr = fmaf(wr_, sr[c], yr);
                    yr = fmaf(-wi_, si[c], yr);
                    yi = fmaf(wr_, si[c], yi);
                    yi = fmaf(wi_, sr[c], yi);
                }
                orj[o][j] = yr; oij[o][j] = yi;
            }
        }
        #pragma unroll
        for (int o = 0; o < 8; o++) {
            *reinterpret_cast<float2*>(outr + o*CHW + t0) = make_float2(orj[o][0], orj[o][1]);
            *reinterpret_cast<float2*>(outi + o*CHW + t0) = make_float2(oij[o][0], oij[o][1]);
        }
    }
}

// ---------------------------------------------------------------------------
extern "C" void kernel_launch(void* const* d_in, const int* in_sizes, int n_in,
                              void* d_out, int out_size)
{
    const float* x     = (const float*)d_in[0];
    const float* cs_wr = (const float*)d_in[1];
    const float* cs_wi = (const float*)d_in[2];
    const float* cs_br = (const float*)d_in[3];
    const float* cs_bi = (const float*)d_in[4];
    const float* fc_wr = (const float*)d_in[5];
    const float* fc_wi = (const float*)d_in[6];
    const float* fc_br = (const float*)d_in[7];
    const float* fc_bi = (const float*)d_in[8];
    const float* tc_wr = (const float*)d_in[9];
    const float* tc_wi = (const float*)d_in[10];
    const float* tc_br = (const float*)d_in[11];
    const float* tc_bi = (const float*)d_in[12];
    const float* ls_wr = (const float*)d_in[13];
    const float* ls_wi = (const float*)d_in[14];
    const float* ls_br = (const float*)d_in[15];
    const float* ls_bi = (const float*)d_in[16];
    const float* la_wr = (const float*)d_in[17];
    const float* la_wi = (const float*)d_in[18];
    const float* la_br = (const float*)d_in[19];
    const float* la_bi = (const float*)d_in[20];
    float* out = (float*)d_out;

    dim3 gA((TN/2 + 255)/256, FF, BB);
    kA<<<gA, 256>>>(x, cs_wr, cs_wi, cs_br, cs_bi);

    dim3 gB((TN/4 + 255)/256, FF, BB*C16);
    kB<<<gB, 256>>>(fc_wr, fc_wi, fc_br, fc_bi);

    kC<<<BB*KC_TSPLIT*FF, KC_THREADS>>>(x, tc_wr, tc_wi, tc_br, tc_bi,
                                        ls_wr, ls_wi, ls_br, ls_bi,
                                        la_wr, la_wi, la_br, la_bi, out);
}